// round 11
// baseline (speedup 1.0000x reference)
#include <cuda_runtime.h>
#include <math.h>

// Problem constants
#define NTOK 2048
#define HIDN 2048
#define NH   16
#define NKV  4
#define DH   128
#define HD   (NH*DH)     // 2048
#define KVD  (NKV*DH)    // 512
#define CH   64
#define NCH  (NTOK/CH)   // 32

// ---------------- scratch (static device globals; no allocation) -------------
__device__ unsigned g_sqT [NTOK*HD];      // roped q, tf32 (attn only)
__device__ float    g_qs  [NTOK*HD];      // softmax q (GLA)
__device__ unsigned g_skT [NTOK*KVD];     // roped k, tf32 (attn only)
__device__ float    g_ks  [NTOK*KVD];     // softmax k (GLA)
__device__ float    g_gl  [NTOK*KVD];
__device__ float    g_v   [NTOK*KVD];     // fp32 v (GLA)
__device__ unsigned g_vT  [NTOK*KVD];     // tf32 v (attn)
__device__ float    g_lam [NTOK*KVD];
__device__ float    g_kdl [NTOK*KVD];
__device__ float    g_dS  [NKV*NCH*DH*DH];
__device__ float    g_S   [NKV*NCH*DH*DH];
__device__ float    g_ltot[NKV*NCH*DH];
__device__ float    g_y   [NTOK*HD];      // 0.5 * attention branch
__device__ float    g_gla [NTOK*HD];      // 0.5 * GLA branch
__device__ unsigned g_cmb [NTOK*HD];      // tf32(y + gla) for the Wo GEMM
__device__ float2   g_rope[NTOK*64];
// pre-rounded tf32 GEMM operands
__device__ unsigned g_hsT [NTOK*HIDN];
__device__ unsigned g_WqT [HIDN*HD];
__device__ unsigned g_WkT [HIDN*KVD];
__device__ unsigned g_WvT [HIDN*KVD];
__device__ unsigned g_WoT [HD*HIDN];

// ---------------- tf32 mma helpers ------------------------------------------
__device__ __forceinline__ unsigned f2tf(float x) {
    unsigned r;
    asm("cvt.rna.tf32.f32 %0, %1;" : "=r"(r) : "f"(x));
    return r;
}

__device__ __forceinline__ uint4 cvt4(float4 v) {
    return make_uint4(f2tf(v.x), f2tf(v.y), f2tf(v.z), f2tf(v.w));
}

__device__ __forceinline__ void mma_tf32(float c[4], const unsigned a[4],
                                         unsigned b0, unsigned b1) {
    asm volatile(
        "mma.sync.aligned.m16n8k8.row.col.f32.tf32.tf32.f32 "
        "{%0,%1,%2,%3}, {%4,%5,%6,%7}, {%8,%9}, {%0,%1,%2,%3};"
        : "+f"(c[0]), "+f"(c[1]), "+f"(c[2]), "+f"(c[3])
        : "r"(a[0]), "r"(a[1]), "r"(a[2]), "r"(a[3]), "r"(b0), "r"(b1));
}

__device__ __forceinline__ void cp16(void* dst, const void* src) {
    unsigned d = (unsigned)__cvta_generic_to_shared(dst);
    asm volatile("cp.async.cg.shared.global [%0], [%1], 16;" :: "r"(d), "l"(src));
}

// =============================================================================
// fp32 -> tf32 pre-rounding. cvt_all handles hs+Wq+Wk+Wv in ONE launch.
// =============================================================================
#define N4_HS (NTOK*HIDN/4)       // 1M
#define N4_WQ (HIDN*HD/4)         // 1M
#define N4_WK (HIDN*KVD/4)        // 256K

__global__ void __launch_bounds__(256) cvt_all_kernel(
    const float4* __restrict__ hs, const float4* __restrict__ Wq,
    const float4* __restrict__ Wk, const float4* __restrict__ Wv)
{
    int i = blockIdx.x * blockDim.x + threadIdx.x;
    if (i < N4_HS) {
        ((uint4*)g_hsT)[i] = cvt4(hs[i]);
    } else if (i < N4_HS + N4_WQ) {
        int j = i - N4_HS;
        ((uint4*)g_WqT)[j] = cvt4(Wq[j]);
    } else if (i < N4_HS + N4_WQ + N4_WK) {
        int j = i - N4_HS - N4_WQ;
        ((uint4*)g_WkT)[j] = cvt4(Wk[j]);
    } else {
        int j = i - N4_HS - N4_WQ - N4_WK;
        ((uint4*)g_WvT)[j] = cvt4(Wv[j]);
    }
}

__global__ void __launch_bounds__(256) cvt_kernel(
    const float4* __restrict__ src, uint4* __restrict__ dst, int n4)
{
    int i = blockIdx.x * blockDim.x + threadIdx.x;
    if (i < n4) dst[i] = cvt4(src[i]);
}

// combine: cmb = tf32(y + gla)
__global__ void __launch_bounds__(256) combine_kernel()
{
    int i = blockIdx.x * blockDim.x + threadIdx.x;   // over NTOK*HD/4
    float4 a = ((const float4*)g_y)[i];
    float4 b = ((const float4*)g_gla)[i];
    ((uint4*)g_cmb)[i] = cvt4(make_float4(a.x + b.x, a.y + b.y, a.z + b.z, a.w + b.w));
}

// =============================================================================
// RoPE cos/sin table
// =============================================================================
__global__ void __launch_bounds__(64) rope_table_kernel()
{
    const int t = blockIdx.x, j = threadIdx.x;
    float inv_freq = (float)pow(10000.0, -(double)(2 * j) / 128.0);
    float fr = (float)t * inv_freq;
    double ang = (double)fr;
    g_rope[t * 64 + j] = make_float2((float)cos(ang), (float)sin(ang));
}

// =============================================================================
// TF32 GEMM v5: 128x128 tile, 256 threads = 8 warps (2m x 4n), warp tile
// 64x32. BK=32, cp.async double-buffered, operands pre-rounded tf32.
// 2 blocks/SM (reg-capped) -> 16 warps/SM for latency hiding.
// =============================================================================
#define AS_STRIDE 36
#define BS_STRIDE 136
#define AS_BUF (128 * AS_STRIDE)
#define BS_BUF (32 * BS_STRIDE)
#define GEMM_SMEM ((2 * AS_BUF + 2 * BS_BUF) * 4)   // 71680 bytes

__device__ __forceinline__ void gemm_issue_slab(
    unsigned* As, unsigned* Bs,
    const unsigned* __restrict__ A, const unsigned* __restrict__ B,
    int N, int K, int bm, int bn, int k0)
{
    const int tid = threadIdx.x;
    // A: 128 rows x 32 cols; thread t -> row t>>1, 16-col half (t&1), 4x cp16
    {
        const int r = tid >> 1, cpart = (tid & 1) * 16;
        const unsigned* src = A + (size_t)(bm + r) * K + k0 + cpart;
        unsigned* dst = As + r * AS_STRIDE + cpart;
#pragma unroll
        for (int q = 0; q < 4; q++) cp16(dst + q * 4, src + q * 4);
    }
    // B: 32 rows x 128 cols; thread t -> row t>>3, col part (t&7)*16, 4x cp16
    {
        const int r = tid >> 3, cpart = (tid & 7) * 16;
        const unsigned* src = B + (size_t)(k0 + r) * N + bn + cpart;
        unsigned* dst = Bs + r * BS_STRIDE + cpart;
#pragma unroll
        for (int q = 0; q < 4; q++) cp16(dst + q * 4, src + q * 4);
    }
}

__device__ __forceinline__ void gemm_tf32_acc(
    unsigned* __restrict__ sm,
    const unsigned* __restrict__ A, const unsigned* __restrict__ B,
    int N, int K, int bm, int bn, float acc[4][4][4])
{
    unsigned* As = sm;
    unsigned* Bs = sm + 2 * AS_BUF;

    const int tid  = threadIdx.x;
    const int warp = tid >> 5, lane = tid & 31;
    const int gid  = lane >> 2, tig = lane & 3;
    const int wm   = (warp & 1) * 64, wn = (warp >> 1) * 32;

#pragma unroll
    for (int mi = 0; mi < 4; mi++)
#pragma unroll
        for (int ni = 0; ni < 4; ni++)
#pragma unroll
            for (int v = 0; v < 4; v++) acc[mi][ni][v] = 0.0f;

    const int nIter = K >> 5;
    gemm_issue_slab(As, Bs, A, B, N, K, bm, bn, 0);
    asm volatile("cp.async.commit_group;");
    if (nIter > 1) {
        gemm_issue_slab(As + AS_BUF, Bs + BS_BUF, A, B, N, K, bm, bn, 32);
    }
    asm volatile("cp.async.commit_group;");

    for (int it = 0; it < nIter; it++) {
        if (it + 1 < nIter)
            asm volatile("cp.async.wait_group 1;");
        else
            asm volatile("cp.async.wait_group 0;");
        __syncthreads();

        const unsigned* as = As + (it & 1) * AS_BUF;
        const unsigned* bs = Bs + (it & 1) * BS_BUF;
#pragma unroll
        for (int k8 = 0; k8 < 4; k8++) {
            unsigned af[4][4];
#pragma unroll
            for (int mi = 0; mi < 4; mi++) {
                int r = wm + mi * 16 + gid;
                af[mi][0] = as[r * AS_STRIDE + k8 * 8 + tig];
                af[mi][1] = as[(r + 8) * AS_STRIDE + k8 * 8 + tig];
                af[mi][2] = as[r * AS_STRIDE + k8 * 8 + tig + 4];
                af[mi][3] = as[(r + 8) * AS_STRIDE + k8 * 8 + tig + 4];
            }
#pragma unroll
            for (int ni = 0; ni < 4; ni++) {
                unsigned b0 = bs[(k8 * 8 + tig) * BS_STRIDE + wn + ni * 8 + gid];
                unsigned b1 = bs[(k8 * 8 + tig + 4) * BS_STRIDE + wn + ni * 8 + gid];
#pragma unroll
                for (int mi = 0; mi < 4; mi++) mma_tf32(acc[mi][ni], af[mi], b0, b1);
            }
        }
        __syncthreads();

        if (it + 2 < nIter) {
            gemm_issue_slab(As + (it & 1) * AS_BUF, Bs + (it & 1) * BS_BUF,
                            A, B, N, K, bm, bn, (it + 2) << 5);
        }
        asm volatile("cp.async.commit_group;");
    }
}

__device__ __forceinline__ void gemm_store(
    float acc[4][4][4], float* __restrict__ C, int N, int bm, int bn)
{
    const int tid  = threadIdx.x;
    const int warp = tid >> 5, lane = tid & 31;
    const int gid  = lane >> 2, tig = lane & 3;
    const int wm   = (warp & 1) * 64, wn = (warp >> 1) * 32;
#pragma unroll
    for (int mi = 0; mi < 4; mi++) {
        int r0 = bm + wm + mi * 16 + gid;
#pragma unroll
        for (int ni = 0; ni < 4; ni++) {
            int col = bn + wn + ni * 8 + tig * 2;
            *(float2*)&C[(size_t)r0 * N + col]       = make_float2(acc[mi][ni][0], acc[mi][ni][1]);
            *(float2*)&C[(size_t)(r0 + 8) * N + col] = make_float2(acc[mi][ni][2], acc[mi][ni][3]);
        }
    }
}

// V store: fp32 for GLA + tf32 shadow for attention.
__device__ __forceinline__ void gemm_store_v(
    float acc[4][4][4], int bm, int bn)
{
    const int tid  = threadIdx.x;
    const int warp = tid >> 5, lane = tid & 31;
    const int gid  = lane >> 2, tig = lane & 3;
    const int wm   = (warp & 1) * 64, wn = (warp >> 1) * 32;
#pragma unroll
    for (int mi = 0; mi < 4; mi++) {
        int r0 = bm + wm + mi * 16 + gid;
#pragma unroll
        for (int ni = 0; ni < 4; ni++) {
            int col = bn + wn + ni * 8 + tig * 2;
            float2 v0 = make_float2(acc[mi][ni][0], acc[mi][ni][1]);
            float2 v1 = make_float2(acc[mi][ni][2], acc[mi][ni][3]);
            *(float2*)&g_v[(size_t)r0 * KVD + col]       = v0;
            *(float2*)&g_v[(size_t)(r0 + 8) * KVD + col] = v1;
            *(uint2*)&g_vT[(size_t)r0 * KVD + col]       = make_uint2(f2tf(v0.x), f2tf(v0.y));
            *(uint2*)&g_vT[(size_t)(r0 + 8) * KVD + col] = make_uint2(f2tf(v1.x), f2tf(v1.y));
        }
    }
}

// Fused prep epilogue (8 warps): softmax -> outs (fp32), RoPE -> outr (tf32
// bits), optional logsigmoid/16 -> outg. Per-row arithmetic identical.
__device__ __forceinline__ void prep_epilogue(
    float acc[4][4][4], unsigned* sm, int bm, int rowstride, int headoff,
    float* __restrict__ outs, unsigned* __restrict__ outr, float* __restrict__ outg)
{
    float* St = (float*)sm;   // [128][132] staging (fits in 71680B)
    const int tid  = threadIdx.x;
    const int warp = tid >> 5, lane = tid & 31;
    const int gid  = lane >> 2, tig = lane & 3;
    const int wm   = (warp & 1) * 64, wn = (warp >> 1) * 32;

#pragma unroll
    for (int mi = 0; mi < 4; mi++) {
        int r0 = wm + mi * 16 + gid;
#pragma unroll
        for (int ni = 0; ni < 4; ni++) {
            int col = wn + ni * 8 + tig * 2;
            *(float2*)&St[r0 * 132 + col]       = make_float2(acc[mi][ni][0], acc[mi][ni][1]);
            *(float2*)&St[(r0 + 8) * 132 + col] = make_float2(acc[mi][ni][2], acc[mi][ni][3]);
        }
    }
    __syncthreads();

    for (int r = warp; r < 128; r += 8) {
        const float* Sr = St + r * 132;
        float x0 = Sr[lane], x1 = Sr[lane + 32], x2 = Sr[lane + 64], x3 = Sr[lane + 96];

        float m = fmaxf(fmaxf(x0, x1), fmaxf(x2, x3));
#pragma unroll
        for (int o = 16; o; o >>= 1) m = fmaxf(m, __shfl_xor_sync(0xffffffffu, m, o));

        float e0 = expf(x0 - m), e1 = expf(x1 - m), e2 = expf(x2 - m), e3 = expf(x3 - m);
        float s = e0 + e1 + e2 + e3;
#pragma unroll
        for (int o = 16; o; o >>= 1) s += __shfl_xor_sync(0xffffffffu, s, o);

        const int t = bm + r;
        const size_t ob = (size_t)t * rowstride + headoff;
        outs[ob + lane]      = e0 / s;
        outs[ob + lane + 32] = e1 / s;
        outs[ob + lane + 64] = e2 / s;
        outs[ob + lane + 96] = e3 / s;

        float2 cs0 = g_rope[t * 64 + lane];
        float2 cs1 = g_rope[t * 64 + lane + 32];
        outr[ob + lane]      = f2tf(x0 * cs0.x - x2 * cs0.y);
        outr[ob + lane + 64] = f2tf(x2 * cs0.x + x0 * cs0.y);
        outr[ob + lane + 32] = f2tf(x1 * cs1.x - x3 * cs1.y);
        outr[ob + lane + 96] = f2tf(x3 * cs1.x + x1 * cs1.y);

        if (outg) {
            outg[ob + lane]      = (fminf(x0, 0.0f) - log1pf(expf(-fabsf(x0)))) * 0.0625f;
            outg[ob + lane + 32] = (fminf(x1, 0.0f) - log1pf(expf(-fabsf(x1)))) * 0.0625f;
            outg[ob + lane + 64] = (fminf(x2, 0.0f) - log1pf(expf(-fabsf(x2)))) * 0.0625f;
            outg[ob + lane + 96] = (fminf(x3, 0.0f) - log1pf(expf(-fabsf(x3)))) * 0.0625f;
        }
    }
}

// Merged q/k/v projections + fused prep.
__global__ void __launch_bounds__(256, 2) proj_kernel()
{
    extern __shared__ unsigned smg[];
    const int bx = blockIdx.x, bm = blockIdx.y * 128;
    float acc[4][4][4];

    if (bx < 16) {
        gemm_tf32_acc(smg, g_hsT, g_WqT, HD, HIDN, bm, bx * 128, acc);
        prep_epilogue(acc, smg, bm, HD, bx * DH, g_qs, g_sqT, nullptr);
    } else if (bx < 20) {
        const int kvh = bx - 16;
        gemm_tf32_acc(smg, g_hsT, g_WkT, KVD, HIDN, bm, kvh * 128, acc);
        prep_epilogue(acc, smg, bm, KVD, kvh * DH, g_ks, g_skT, g_gl);
    } else {
        gemm_tf32_acc(smg, g_hsT, g_WvT, KVD, HIDN, bm, (bx - 20) * 128, acc);
        gemm_store_v(acc, bm, (bx - 20) * 128);
    }
}

// Output projection: out = cmb @ Wo (both pre-rounded tf32)
__global__ void __launch_bounds__(256, 2) wo_kernel(float* __restrict__ out)
{
    extern __shared__ unsigned smg[];
    float acc[4][4][4];
    gemm_tf32_acc(smg, g_cmb, g_WoT, HIDN, HD, blockIdx.y * 128, blockIdx.x * 128, acc);
    gemm_store(acc, out, HIDN, blockIdx.y * 128, blockIdx.x * 128);
}

// =============================================================================
// GLA pass 1: grid (NCH, NKV, 2) — z selects a 64-wide d-half.
// =============================================================================
#define P1_SMEM ((64 * 68 * 2 + 64 * 132 + 64) * 4)

__global__ void __launch_bounds__(256) gla_pass1_kernel()
{
    extern __shared__ float sm1[];
    float* GL   = sm1;                 // [64][68]
    float* KW   = GL + 64 * 68;        // [64][68]
    float* Vt   = KW + 64 * 68;        // [64][132]
    float* LEND = Vt + 64 * 132;       // [64]

    const int c = blockIdx.x, kvh = blockIdx.y, z = blockIdx.z;
    const int dbase = z * 64;
    const int tid = threadIdx.x;

    for (int i = tid; i < 64 * 64; i += 256) {
        int r = i >> 6, d = i & 63;
        GL[r * 68 + d] = g_gl[(c * CH + r) * KVD + kvh * DH + dbase + d];
    }
    for (int i = tid; i < 64 * 128; i += 256) {
        int r = i >> 7, d = i & 127;
        Vt[r * 132 + d] = g_v[(c * CH + r) * KVD + kvh * DH + d];
    }
    __syncthreads();

    if (tid < 64) {
        float cum = 0.0f;
#pragma unroll 4
        for (int t = 0; t < CH; t++) {
            cum += GL[t * 68 + tid];
            GL[t * 68 + tid] = expf(cum);
        }
        float le = GL[63 * 68 + tid];
        LEND[tid] = le;
        g_ltot[(kvh * NCH + c) * DH + dbase + tid] = le;
    }
    __syncthreads();

    for (int i = tid; i < 64 * 64; i += 256) {
        int r = i >> 6, d = i & 63;
        int gi = (c * CH + r) * KVD + kvh * DH + dbase + d;
        float lam = GL[r * 68 + d];
        float kdl = g_ks[gi] / lam;
        g_kdl[gi] = kdl;
        g_lam[gi] = lam;
        KW[r * 68 + d] = kdl * LEND[d];
    }
    __syncthreads();

    const int tx = tid & 15, ty = tid >> 4;
    float acc[4][8];
#pragma unroll
    for (int i = 0; i < 4; i++)
#pragma unroll
        for (int j = 0; j < 8; j++) acc[i][j] = 0.0f;

    for (int t = 0; t < CH; t++) {
        float a[4], b[8];
        *(float4*)&a[0] = *(const float4*)&KW[t * 68 + ty * 4];
        *(float4*)&b[0] = *(const float4*)&Vt[t * 132 + tx * 8];
        *(float4*)&b[4] = *(const float4*)&Vt[t * 132 + tx * 8 + 4];
#pragma unroll
        for (int i = 0; i < 4; i++)
#pragma unroll
            for (int j = 0; j < 8; j++) acc[i][j] += a[i] * b[j];
    }

    float* dS = g_dS + (size_t)(kvh * NCH + c) * DH * DH + (size_t)dbase * DH;
#pragma unroll
    for (int i = 0; i < 4; i++) {
        *(float4*)&dS[(ty * 4 + i) * DH + tx * 8]     = make_float4(acc[i][0], acc[i][1], acc[i][2], acc[i][3]);
        *(float4*)&dS[(ty * 4 + i) * DH + tx * 8 + 4] = make_float4(acc[i][4], acc[i][5], acc[i][6], acc[i][7]);
    }
}

// =============================================================================
// GLA pass 2: scan over chunks (separate src/dst, register prefetch).
// =============================================================================
__global__ void __launch_bounds__(128) gla_scan_kernel()
{
    const int kvh = blockIdx.x, d = blockIdx.y;
    const int dp = threadIdx.x;

    __shared__ float lt[NCH];
    if (dp < NCH) lt[dp] = g_ltot[(kvh * NCH + dp) * DH + d];
    __syncthreads();

    const size_t base = (size_t)(kvh * NCH) * DH * DH + (size_t)d * DH + dp;
    const float* __restrict__ src = g_dS + base;
    float* __restrict__ dst = g_S + base;
    const size_t step = (size_t)DH * DH;

    float s = 0.0f;
    float pre[4];
#pragma unroll
    for (int c = 0; c < 4; c++) pre[c] = src[c * step];
#pragma unroll
    for (int c = 0; c < NCH; c++) {
        float v = pre[c & 3];
        if (c + 4 < NCH) pre[c & 3] = src[(c + 4) * step];
        dst[c * step] = s;
        s = s * lt[c] + v;
    }
}

// =============================================================================
// GLA pass 3 (fp32 SIMT, 512 threads): writes 0.5*o_gla into g_gla.
// =============================================================================
__global__ void __launch_bounds__(512) gla_pass3_kernel()
{
    extern __shared__ float sm3[];
    float* QT = sm3;               // [128][65]
    float* KT = QT + 128 * 65;
    float* Ss = KT + 128 * 65;     // [128][132]
    float* Vs = Ss + 128 * 132;    // [64][132]
    float* AT = Vs + 64 * 132;     // [64][65]

    const int c = blockIdx.x, h = blockIdx.y;
    const int kvh = h >> 2;
    const int tid = threadIdx.x;

    for (int idx = tid; idx < CH * DH; idx += 512) {
        int r = idx >> 7, d = idx & 127;
        int kb = (c * CH + r) * KVD + kvh * DH + d;
        float lam = g_lam[kb];
        QT[d * 65 + r] = g_qs[(c * CH + r) * HD + h * DH + d] * lam;
        KT[d * 65 + r] = g_kdl[kb];
        Vs[r * 132 + d] = g_v[kb];
    }
    const float* Sg = g_S + (size_t)(kvh * NCH + c) * DH * DH;
    for (int idx = tid; idx < DH * DH; idx += 512) {
        int r = idx >> 7, d = idx & 127;
        Ss[r * 132 + d] = Sg[r * DH + d];
    }
    __syncthreads();

    const int tx = tid & 15, ty = tid >> 4;   // ty 0..31

    float O[2][8];
#pragma unroll
    for (int i = 0; i < 2; i++)
#pragma unroll
        for (int j = 0; j < 8; j++) O[i][j] = 0.0f;

    for (int dd = 0; dd < DH; dd++) {
        float a[2], b[8];
#pragma unroll
        for (int i = 0; i < 2; i++) a[i] = QT[dd * 65 + ty * 2 + i];
        *(float4*)&b[0] = *(const float4*)&Ss[dd * 132 + tx * 8];
        *(float4*)&b[4] = *(const float4*)&Ss[dd * 132 + tx * 8 + 4];
#pragma unroll
        for (int i = 0; i < 2; i++)
#pragma unroll
            for (int j = 0; j < 8; j++) O[i][j] += a[i] * b[j];
    }

    float Aacc[2][4];
#pragma unroll
    for (int i = 0; i < 2; i++)
#pragma unroll
        for (int j = 0; j < 4; j++) Aacc[i][j] = 0.0f;

    for (int dd = 0; dd < DH; dd++) {
        float a[2], b[4];
#pragma unroll
        for (int i = 0; i < 2; i++) a[i] = QT[dd * 65 + ty * 2 + i];
#pragma unroll
        for (int j = 0; j < 4; j++) b[j] = KT[dd * 65 + tx * 4 + j];
#pragma unroll
        for (int i = 0; i < 2; i++)
#pragma unroll
            for (int j = 0; j < 4; j++) Aacc[i][j] += a[i] * b[j];
    }
#pragma unroll
    for (int i = 0; i < 2; i++)
#pragma unroll
        for (int j = 0; j < 4; j++) {
            int t = ty * 2 + i, s = tx * 4 + j;
            AT[s * 65 + t] = (s <= t) ? Aacc[i][j] : 0.0f;
        }
    __syncthreads();

    for (int s = 0; s < CH; s++) {
        float a[2], b[8];
#pragma unroll
        for (int i = 0; i < 2; i++) a[i] = AT[s * 65 + ty * 2 + i];
        *(float4*)&b[0] = *(const float4*)&Vs[s * 132 + tx * 8];
        *(float4*)&b[4] = *(const float4*)&Vs[s * 132 + tx * 8 + 4];
#pragma unroll
        for (int i = 0; i < 2; i++)
#pragma unroll
            for (int j = 0; j < 8; j++) O[i][j] += a[i] * b[j];
    }

#pragma unroll
    for (int i = 0; i < 2; i++) {
        int t = c * CH + ty * 2 + i;
        float4 o0 = make_float4(0.5f*O[i][0], 0.5f*O[i][1], 0.5f*O[i][2], 0.5f*O[i][3]);
        float4 o1 = make_float4(0.5f*O[i][4], 0.5f*O[i][5], 0.5f*O[i][6], 0.5f*O[i][7]);
        *(float4*)&g_gla[t * HD + h * DH + tx * 8]     = o0;
        *(float4*)&g_gla[t * HD + h * DH + tx * 8 + 4] = o1;
    }
}

// =============================================================================
// Causal flash attention: all operands pre-rounded tf32 — zero cvt in the
// hot loops. Writes 0.5*y into g_y (concurrent with the GLA chain).
// =============================================================================
#define ATTN_SMEM ((128*132 + 2*64*132 + 64*136 + 8*16*68) * 4)   // 204800 B

__global__ void __launch_bounds__(256) attn_tc_kernel()
{
    extern __shared__ char smraw[];
    unsigned* Qs = (unsigned*)smraw;                                    // [128][132]
    unsigned* Ks = (unsigned*)(smraw + 128 * 132 * 4);                  // [2][64][132]
    unsigned* Vs = (unsigned*)(smraw + (128 * 132 + 2 * 64 * 132) * 4); // [64][136]
    unsigned* Pb = (unsigned*)(smraw + (128 * 132 + 2 * 64 * 132 + 64 * 136) * 4);

    const int qt = gridDim.x - 1 - blockIdx.x;
    const int h = blockIdx.y;
    const int kvh = h >> 2;
    const int tid = threadIdx.x;
    const int warp = tid >> 5, lane = tid & 31;
    const int gid = lane >> 2, tig = lane & 3;
    unsigned* Pw = Pb + warp * 16 * 68;
    const float scale = 0.08838834764831845f;
    const int ktmax = 2 * qt + 1;

    {
#pragma unroll
        for (int i = 0; i < 8; i++) {
            int idx = tid + i * 256;
            int r = idx >> 5, c4 = (idx & 31) * 4;
            cp16(&Ks[r * 132 + c4], &g_skT[(size_t)r * KVD + kvh * DH + c4]);
        }
        asm volatile("cp.async.commit_group;");
    }

    for (int i = tid; i < 128 * 32; i += 256) {
        int r = i >> 5, c4 = (i & 31) * 4;
        *(uint4*)&Qs[r * 132 + c4] =
            *(const uint4*)&g_sqT[(size_t)(qt * 128 + r) * HD + h * DH + c4];
    }

    const int rbase = qt * 128 + warp * 16;
    float m_i[2] = {-1e30f, -1e30f};
    float l_i[2] = {0.0f, 0.0f};
    float c[16][4];
#pragma unroll
    for (int ni = 0; ni < 16; ni++)
#pragma unroll
        for (int v = 0; v < 4; v++) c[ni][v] = 0.0f;

    for (int kt = 0; kt <= ktmax; kt++) {
        __syncthreads();

#pragma unroll
        for (int i = 0; i < 8; i++) {
            int idx = tid + i * 256;
            int r = idx >> 5, c4 = (idx & 31) * 4;
            cp16(&Vs[r * 136 + c4], &g_vT[(size_t)(kt * 64 + r) * KVD + kvh * DH + c4]);
        }
        asm volatile("cp.async.commit_group;");

        {
            const int ktn = (kt < ktmax) ? kt + 1 : kt;
            unsigned* KB = Ks + ((kt + 1) & 1) * 64 * 132;
#pragma unroll
            for (int i = 0; i < 8; i++) {
                int idx = tid + i * 256;
                int r = idx >> 5, c4 = (idx & 31) * 4;
                cp16(&KB[r * 132 + c4], &g_skT[(size_t)(ktn * 64 + r) * KVD + kvh * DH + c4]);
            }
            asm volatile("cp.async.commit_group;");
        }

        asm volatile("cp.async.wait_group 2;");
        __syncthreads();

        const unsigned* KB = Ks + (kt & 1) * 64 * 132;
        const int smin = kt * 64;
        const bool active = (smin <= rbase + 15);

        if (active) {
            float sacc[8][4];
#pragma unroll
            for (int ni = 0; ni < 8; ni++)
#pragma unroll
                for (int v = 0; v < 4; v++) sacc[ni][v] = 0.0f;

#pragma unroll 4
            for (int k8 = 0; k8 < 16; k8++) {
                unsigned aq[4];
                int qr = warp * 16 + gid;
                aq[0] = Qs[qr * 132 + k8 * 8 + tig];
                aq[1] = Qs[(qr + 8) * 132 + k8 * 8 + tig];
                aq[2] = Qs[qr * 132 + k8 * 8 + tig + 4];
                aq[3] = Qs[(qr + 8) * 132 + k8 * 8 + tig + 4];
#pragma unroll
                for (int ni = 0; ni < 8; ni++) {
                    unsigned b0 = KB[(ni * 8 + gid) * 132 + k8 * 8 + tig];
                    unsigned b1 = KB[(ni * 8 + gid) * 132 + k8 * 8 + tig + 4];
                    mma_tf32(sacc[ni], aq, b0, b1);
                }
            }

            const bool partial = (smin + 63 > rbase);
#pragma unroll
            for (int ni = 0; ni < 8; ni++)
#pragma unroll
                for (int v = 0; v < 4; v++) {
                    float sv = sacc[ni][v] * scale;
                    if (partial) {
                        int row = rbase + gid + (v >> 1) * 8;
                        int col = smin + ni * 8 + tig * 2 + (v & 1);
                        if (col > row) sv = -1e30f;
                    }
                    sacc[ni][v] = sv;
                }

#pragma unroll
            for (int h2 = 0; h2 < 2; h2++) {
                float rmax = -1e30f;
#pragma unroll
                for (int ni = 0; ni < 8; ni++)
                    rmax = fmaxf(rmax, fmaxf(sacc[ni][2 * h2], sacc[ni][2 * h2 + 1]));
                rmax = fmaxf(rmax, __shfl_xor_sync(0xffffffffu, rmax, 1));
                rmax = fmaxf(rmax, __shfl_xor_sync(0xffffffffu, rmax, 2));
                float mnew = fmaxf(m_i[h2], rmax);
                float alpha = __expf(m_i[h2] - mnew);
                float rsum = 0.0f;
#pragma unroll
                for (int ni = 0; ni < 8; ni++) {
                    float p0 = __expf(sacc[ni][2 * h2] - mnew);
                    float p1 = __expf(sacc[ni][2 * h2 + 1] - mnew);
                    sacc[ni][2 * h2] = p0;
                    sacc[ni][2 * h2 + 1] = p1;
                    rsum += p0 + p1;
                }
                rsum += __shfl_xor_sync(0xffffffffu, rsum, 1);
                rsum += __shfl_xor_sync(0xffffffffu, rsum, 2);
                l_i[h2] = l_i[h2] * alpha + rsum;
                m_i[h2] = mnew;
#pragma unroll
                for (int ni = 0; ni < 16; ni++) {
                    c[ni][2 * h2]     *= alpha;
                    c[ni][2 * h2 + 1] *= alpha;
                }
            }

#pragma unroll
            for (int ni = 0; ni < 8; ni++) {
                *(uint2*)&Pw[gid * 68 + ni * 8 + tig * 2] =
                    make_uint2(f2tf(sacc[ni][0]), f2tf(sacc[ni][1]));
                *(uint2*)&Pw[(gid + 8) * 68 + ni * 8 + tig * 2] =
                    make_uint2(f2tf(sacc[ni][2]), f2tf(sacc[ni][3]));
            }
        }

        asm volatile("cp.async.wait_group 1;");
        __syncthreads();

        if (active) {
#pragma unroll 2
            for (int k8 = 0; k8 < 8; k8++) {
                unsigned ap[4];
                ap[0] = Pw[gid * 68 + k8 * 8 + tig];
                ap[1] = Pw[(gid + 8) * 68 + k8 * 8 + tig];
                ap[2] = Pw[gid * 68 + k8 * 8 + tig + 4];
                ap[3] = Pw[(gid + 8) * 68 + k8 * 8 + tig + 4];
#pragma unroll
                for (int ni = 0; ni < 16; ni++) {
                    unsigned b0 = Vs[(k8 * 8 + tig) * 136 + ni * 8 + gid];
                    unsigned b1 = Vs[(k8 * 8 + tig + 4) * 136 + ni * 8 + gid];
                    mma_tf32(c[ni], ap, b0, b1);
                }
            }
        }
    }

    const float h0 = 0.5f / l_i[0];
    const float h1 = 0.5f / l_i[1];
    const int r0 = rbase + gid, r1 = r0 + 8;
#pragma unroll
    for (int ni = 0; ni < 16; ni++) {
        int col = h * DH + ni * 8 + tig * 2;
        *(float2*)&g_y[(size_t)r0 * HD + col] = make_float2(c[ni][0] * h0, c[ni][1] * h0);
        *(float2*)&g_y[(size_t)r1 * HD + col] = make_float2(c[ni][2] * h1, c[ni][3] * h1);
    }
}

// =============================================================================
// host launcher — fork/join: GLA chain (stream A) || attention (stream B)
// =============================================================================
extern "C" void kernel_launch(void* const* d_in, const int* in_sizes, int n_in,
                              void* d_out, int out_size)
{
    (void)in_sizes; (void)n_in; (void)out_size;
    const float* hs = (const float*)d_in[0];
    const float* Wq = (const float*)d_in[1];
    const float* Wk = (const float*)d_in[2];
    const float* Wv = (const float*)d_in[3];
    const float* Wo = (const float*)d_in[4];
    float* out = (float*)d_out;

    unsigned* p_WoT;
    cudaGetSymbolAddress((void**)&p_WoT, g_WoT);

    static cudaStream_t sA = nullptr, sB = nullptr;
    static cudaEvent_t ev0, evP, evA, evB;
    if (sA == nullptr) {
        cudaStreamCreateWithFlags(&sA, cudaStreamNonBlocking);
        cudaStreamCreateWithFlags(&sB, cudaStreamNonBlocking);
        cudaEventCreateWithFlags(&ev0, cudaEventDisableTiming);
        cudaEventCreateWithFlags(&evP, cudaEventDisableTiming);
        cudaEventCreateWithFlags(&evA, cudaEventDisableTiming);
        cudaEventCreateWithFlags(&evB, cudaEventDisableTiming);
    }

    const int smem3 = (2 * 128 * 65 + 128 * 132 + 64 * 132 + 64 * 65) * 4;
    cudaFuncSetAttribute(proj_kernel,      cudaFuncAttributeMaxDynamicSharedMemorySize, GEMM_SMEM);
    cudaFuncSetAttribute(wo_kernel,        cudaFuncAttributeMaxDynamicSharedMemorySize, GEMM_SMEM);
    cudaFuncSetAttribute(gla_pass1_kernel, cudaFuncAttributeMaxDynamicSharedMemorySize, P1_SMEM);
    cudaFuncSetAttribute(gla_pass3_kernel, cudaFuncAttributeMaxDynamicSharedMemorySize, smem3);
    cudaFuncSetAttribute(attn_tc_kernel,   cudaFuncAttributeMaxDynamicSharedMemorySize, ATTN_SMEM);

    // --- fork Wo conversion onto stream A early (only wo needs it) ---
    cudaEventRecord(ev0, 0);
    cudaStreamWaitEvent(sA, ev0, 0);
    cvt_kernel<<<4096, 256, 0, sA>>>((const float4*)Wo, (uint4*)p_WoT, HD * HIDN / 4);

    // --- main stream: rope table + fused operand pre-rounding + projections ---
    rope_table_kernel<<<NTOK, 64>>>();
    cvt_all_kernel<<<(N4_HS + N4_WQ + 2 * N4_WK) / 256, 256>>>(
        (const float4*)hs, (const float4*)Wq, (const float4*)Wk, (const float4*)Wv);
    proj_kernel<<<dim3(24, 16), 256, GEMM_SMEM>>>();
    cudaEventRecord(evP, 0);

    // --- stream A: GLA chain ---
    cudaStreamWaitEvent(sA, evP, 0);
    gla_pass1_kernel<<<dim3(NCH, NKV, 2), 256, P1_SMEM, sA>>>();
    gla_scan_kernel<<<dim3(NKV, DH), 128, 0, sA>>>();
    gla_pass3_kernel<<<dim3(NCH, NH), 512, smem3, sA>>>();
    cudaEventRecord(evA, sA);

    // --- stream B: causal flash attention (concurrent with GLA chain) ---
    cudaStreamWaitEvent(sB, evP, 0);
    attn_tc_kernel<<<dim3(NTOK / 128, NH), 256, ATTN_SMEM, sB>>>();
    cudaEventRecord(evB, sB);

    // --- join, combine, output projection ---
    cudaStreamWaitEvent(0, evA, 0);
    cudaStreamWaitEvent(0, evB, 0);
    combine_kernel<<<NTOK * HD / 4 / 256, 256>>>();
    wo_kernel<<<dim3(16, 16), 256, GEMM_SMEM>>>(out);
}

// round 14
// speedup vs baseline: 1.3469x; 1.3469x over previous
#include <cuda_runtime.h>
#include <cuda_fp16.h>
#include <math.h>

// Problem constants
#define NTOK 2048
#define HIDN 2048
#define NH   16
#define NKV  4
#define DH   128
#define HD   (NH*DH)     // 2048
#define KVD  (NKV*DH)    // 512
#define CH   64
#define NCH  (NTOK/CH)   // 32

// ---------------- scratch (static device globals; no allocation) -------------
__device__ unsigned g_sqT [NTOK*HD];      // roped q, tf32 (attn only)
__device__ float    g_qs  [NTOK*HD];      // softmax q (GLA)
__device__ unsigned g_skT [NTOK*KVD];     // roped k, tf32 (attn only)
__device__ float    g_ks  [NTOK*KVD];     // softmax k (GLA)
__device__ float    g_gl  [NTOK*KVD];
__device__ float    g_v   [NTOK*KVD];     // fp32 v (GLA)
__device__ unsigned g_vT  [NTOK*KVD];     // tf32 v (attn)
__device__ float    g_lam [NTOK*KVD];
__device__ float    g_kdl [NTOK*KVD];
__device__ float    g_dS  [NKV*NCH*DH*DH];
__device__ float    g_S   [NKV*NCH*DH*DH];
__device__ float    g_ltot[NKV*NCH*DH];
__device__ float    g_y   [NTOK*HD];      // 0.5 * attention branch
__device__ float    g_gla [NTOK*HD];      // 0.5 * GLA branch
__device__ float2   g_rope[NTOK*64];
// fp16 GEMM operands (packed half2 words). Weights TRANSPOSED to [N][K].
__device__ unsigned g_hsH [NTOK*HIDN/2];
__device__ unsigned g_WqH [HD*HIDN/2];    // [N=2048][K=2048]
__device__ unsigned g_WkH [KVD*HIDN/2];   // [N=512][K=2048]
__device__ unsigned g_WvH [KVD*HIDN/2];
__device__ unsigned g_WoH [HIDN*HD/2];    // [N=2048][K=2048]
__device__ unsigned g_cmbH[NTOK*HD/2];    // fp16(y + gla)

// ---------------- helpers ----------------------------------------------------
__device__ __forceinline__ unsigned f2tf(float x) {
    unsigned r;
    asm("cvt.rna.tf32.f32 %0, %1;" : "=r"(r) : "f"(x));
    return r;
}

__device__ __forceinline__ unsigned f2h2(float a, float b) {
    __half2 h = __floats2half2_rn(a, b);
    return *(unsigned*)&h;
}

// tf32 mma (attention only)
__device__ __forceinline__ void mma_tf32(float c[4], const unsigned a[4],
                                         unsigned b0, unsigned b1) {
    asm volatile(
        "mma.sync.aligned.m16n8k8.row.col.f32.tf32.tf32.f32 "
        "{%0,%1,%2,%3}, {%4,%5,%6,%7}, {%8,%9}, {%0,%1,%2,%3};"
        : "+f"(c[0]), "+f"(c[1]), "+f"(c[2]), "+f"(c[3])
        : "r"(a[0]), "r"(a[1]), "r"(a[2]), "r"(a[3]), "r"(b0), "r"(b1));
}

// fp16 mma (GEMMs): m16n8k16, fp32 accumulate
__device__ __forceinline__ void mma_f16(float c[4], const unsigned a[4],
                                        unsigned b0, unsigned b1) {
    asm volatile(
        "mma.sync.aligned.m16n8k16.row.col.f32.f16.f16.f32 "
        "{%0,%1,%2,%3}, {%4,%5,%6,%7}, {%8,%9}, {%0,%1,%2,%3};"
        : "+f"(c[0]), "+f"(c[1]), "+f"(c[2]), "+f"(c[3])
        : "r"(a[0]), "r"(a[1]), "r"(a[2]), "r"(a[3]), "r"(b0), "r"(b1));
}

__device__ __forceinline__ void cp16(void* dst, const void* src) {
    unsigned d = (unsigned)__cvta_generic_to_shared(dst);
    asm volatile("cp.async.cg.shared.global [%0], [%1], 16;" :: "r"(d), "l"(src));
}

// =============================================================================
// fp32 -> fp16 packing (hs) and transpose+pack (weights -> [N][K])
// =============================================================================
__global__ void __launch_bounds__(256) cvt_h_kernel(
    const float4* __restrict__ src, uint2* __restrict__ dst, int n4)
{
    int i = blockIdx.x * blockDim.x + threadIdx.x;
    if (i < n4) {
        float4 v = src[i];
        dst[i] = make_uint2(f2h2(v.x, v.y), f2h2(v.z, v.w));
    }
}

__global__ void __launch_bounds__(256) transpose_cvt_h_kernel(
    const float* __restrict__ src, __half* __restrict__ dst, int K, int N)
{
    __shared__ float tile[32][33];
    const int n0 = blockIdx.x * 32, k0 = blockIdx.y * 32;
    const int tx = threadIdx.x & 31, ty = threadIdx.x >> 5;
#pragma unroll
    for (int p = 0; p < 4; p++)
        tile[ty + p * 8][tx] = src[(size_t)(k0 + ty + p * 8) * N + n0 + tx];
    __syncthreads();
#pragma unroll
    for (int p = 0; p < 4; p++)
        dst[(size_t)(n0 + ty + p * 8) * K + k0 + tx] = __float2half_rn(tile[tx][ty + p * 8]);
}

// combine: cmbH = fp16(y + gla)
__global__ void __launch_bounds__(256) combine_kernel()
{
    int i = blockIdx.x * blockDim.x + threadIdx.x;   // over NTOK*HD/4
    float4 a = ((const float4*)g_y)[i];
    float4 b = ((const float4*)g_gla)[i];
    ((uint2*)g_cmbH)[i] = make_uint2(f2h2(a.x + b.x, a.y + b.y),
                                     f2h2(a.z + b.z, a.w + b.w));
}

// =============================================================================
// RoPE cos/sin table
// =============================================================================
__global__ void __launch_bounds__(64) rope_table_kernel()
{
    const int t = blockIdx.x, j = threadIdx.x;
    float inv_freq = (float)pow(10000.0, -(double)(2 * j) / 128.0);
    float fr = (float)t * inv_freq;
    double ang = (double)fr;
    g_rope[t * 64 + j] = make_float2((float)cos(ang), (float)sin(ang));
}

// =============================================================================
// FP16 GEMM v6: D[128x128] = A[128xK] @ B[128xK]^T (both [rows][K] half-pairs).
// 256 threads = 8 warps (2m x 4n), warp tile 64x32. BK=32 halves (16 words),
// cp.async double-buffered, stride 20 words (conflict-free fragments).
// =============================================================================
#define ASW 20                    // smem row stride in words
#define ABUFW (128 * ASW)         // 2560 words per buffer
#define GEMM_SMEM (128 * 132 * 4) // 67584 B (St overlay; buffers use 40960 B)

__device__ __forceinline__ void gemm_issue_h(
    unsigned* As, unsigned* Bs,
    const unsigned* __restrict__ A, const unsigned* __restrict__ B,
    int Kw, int bm, int bn, int k0w)
{
    const int t = threadIdx.x;
    const int r = t >> 1, h8 = (t & 1) * 8;
    {
        const unsigned* src = &A[(size_t)(bm + r) * Kw + k0w + h8];
        unsigned* dst = &As[r * ASW + h8];
        cp16(dst, src);
        cp16(dst + 4, src + 4);
    }
    {
        const unsigned* src = &B[(size_t)(bn + r) * Kw + k0w + h8];
        unsigned* dst = &Bs[r * ASW + h8];
        cp16(dst, src);
        cp16(dst + 4, src + 4);
    }
}

__device__ __forceinline__ void gemm_f16_acc(
    unsigned* __restrict__ smw,
    const unsigned* __restrict__ A, const unsigned* __restrict__ B,
    int Kw, int bm, int bn, float acc[4][4][4])
{
    unsigned* As = smw;
    unsigned* Bs = smw + 2 * ABUFW;

    const int tid  = threadIdx.x;
    const int warp = tid >> 5, lane = tid & 31;
    const int gid  = lane >> 2, tig = lane & 3;
    const int wm   = (warp & 1) * 64, wn = (warp >> 1) * 32;

#pragma unroll
    for (int mi = 0; mi < 4; mi++)
#pragma unroll
        for (int ni = 0; ni < 4; ni++)
#pragma unroll
            for (int v = 0; v < 4; v++) acc[mi][ni][v] = 0.0f;

    const int nIter = Kw >> 4;   // 16 words per slab
    gemm_issue_h(As, Bs, A, B, Kw, bm, bn, 0);
    asm volatile("cp.async.commit_group;");
    if (nIter > 1) {
        gemm_issue_h(As + ABUFW, Bs + ABUFW, A, B, Kw, bm, bn, 16);
    }
    asm volatile("cp.async.commit_group;");

    for (int it = 0; it < nIter; it++) {
        if (it + 1 < nIter)
            asm volatile("cp.async.wait_group 1;");
        else
            asm volatile("cp.async.wait_group 0;");
        __syncthreads();

        const unsigned* as = As + (it & 1) * ABUFW;
        const unsigned* bs = Bs + (it & 1) * ABUFW;
#pragma unroll
        for (int step = 0; step < 2; step++) {
            unsigned af[4][4];
#pragma unroll
            for (int mi = 0; mi < 4; mi++) {
                int r = wm + mi * 16 + gid;
                af[mi][0] = as[r * ASW + step * 8 + tig];
                af[mi][1] = as[(r + 8) * ASW + step * 8 + tig];
                af[mi][2] = as[r * ASW + step * 8 + tig + 4];
                af[mi][3] = as[(r + 8) * ASW + step * 8 + tig + 4];
            }
#pragma unroll
            for (int ni = 0; ni < 4; ni++) {
                unsigned b0 = bs[(wn + ni * 8 + gid) * ASW + step * 8 + tig];
                unsigned b1 = bs[(wn + ni * 8 + gid) * ASW + step * 8 + tig + 4];
#pragma unroll
                for (int mi = 0; mi < 4; mi++) mma_f16(acc[mi][ni], af[mi], b0, b1);
            }
        }
        __syncthreads();

        if (it + 2 < nIter) {
            // slab (it+2) -> buffer ((it+2)&1) == (it&1), the one just consumed
            gemm_issue_h(As + (it & 1) * ABUFW, Bs + (it & 1) * ABUFW,
                         A, B, Kw, bm, bn, (it + 2) * 16);
        }
        asm volatile("cp.async.commit_group;");
    }
}

__device__ __forceinline__ void gemm_store(
    float acc[4][4][4], float* __restrict__ C, int N, int bm, int bn)
{
    const int tid  = threadIdx.x;
    const int warp = tid >> 5, lane = tid & 31;
    const int gid  = lane >> 2, tig = lane & 3;
    const int wm   = (warp & 1) * 64, wn = (warp >> 1) * 32;
#pragma unroll
    for (int mi = 0; mi < 4; mi++) {
        int r0 = bm + wm + mi * 16 + gid;
#pragma unroll
        for (int ni = 0; ni < 4; ni++) {
            int col = bn + wn + ni * 8 + tig * 2;
            *(float2*)&C[(size_t)r0 * N + col]       = make_float2(acc[mi][ni][0], acc[mi][ni][1]);
            *(float2*)&C[(size_t)(r0 + 8) * N + col] = make_float2(acc[mi][ni][2], acc[mi][ni][3]);
        }
    }
}

// V store: fp32 for GLA + tf32 shadow for attention.
__device__ __forceinline__ void gemm_store_v(
    float acc[4][4][4], int bm, int bn)
{
    const int tid  = threadIdx.x;
    const int warp = tid >> 5, lane = tid & 31;
    const int gid  = lane >> 2, tig = lane & 3;
    const int wm   = (warp & 1) * 64, wn = (warp >> 1) * 32;
#pragma unroll
    for (int mi = 0; mi < 4; mi++) {
        int r0 = bm + wm + mi * 16 + gid;
#pragma unroll
        for (int ni = 0; ni < 4; ni++) {
            int col = bn + wn + ni * 8 + tig * 2;
            float2 v0 = make_float2(acc[mi][ni][0], acc[mi][ni][1]);
            float2 v1 = make_float2(acc[mi][ni][2], acc[mi][ni][3]);
            *(float2*)&g_v[(size_t)r0 * KVD + col]       = v0;
            *(float2*)&g_v[(size_t)(r0 + 8) * KVD + col] = v1;
            *(uint2*)&g_vT[(size_t)r0 * KVD + col]       = make_uint2(f2tf(v0.x), f2tf(v0.y));
            *(uint2*)&g_vT[(size_t)(r0 + 8) * KVD + col] = make_uint2(f2tf(v1.x), f2tf(v1.y));
        }
    }
}

// Fused prep epilogue (8 warps): stages acc in smem (overlays GEMM buffers —
// safe after the mainloop's final __syncthreads), then per row: softmax ->
// outs (fp32), RoPE -> outr (tf32 bits), optional logsigmoid/16 -> outg.
__device__ __forceinline__ void prep_epilogue(
    float acc[4][4][4], unsigned* smw, int bm, int rowstride, int headoff,
    float* __restrict__ outs, unsigned* __restrict__ outr, float* __restrict__ outg)
{
    float* St = (float*)smw;   // [128][132]
    const int tid  = threadIdx.x;
    const int warp = tid >> 5, lane = tid & 31;
    const int gid  = lane >> 2, tig = lane & 3;
    const int wm   = (warp & 1) * 64, wn = (warp >> 1) * 32;

#pragma unroll
    for (int mi = 0; mi < 4; mi++) {
        int r0 = wm + mi * 16 + gid;
#pragma unroll
        for (int ni = 0; ni < 4; ni++) {
            int col = wn + ni * 8 + tig * 2;
            *(float2*)&St[r0 * 132 + col]       = make_float2(acc[mi][ni][0], acc[mi][ni][1]);
            *(float2*)&St[(r0 + 8) * 132 + col] = make_float2(acc[mi][ni][2], acc[mi][ni][3]);
        }
    }
    __syncthreads();

    for (int r = warp; r < 128; r += 8) {
        const float* Sr = St + r * 132;
        float x0 = Sr[lane], x1 = Sr[lane + 32], x2 = Sr[lane + 64], x3 = Sr[lane + 96];

        float m = fmaxf(fmaxf(x0, x1), fmaxf(x2, x3));
#pragma unroll
        for (int o = 16; o; o >>= 1) m = fmaxf(m, __shfl_xor_sync(0xffffffffu, m, o));

        float e0 = expf(x0 - m), e1 = expf(x1 - m), e2 = expf(x2 - m), e3 = expf(x3 - m);
        float s = e0 + e1 + e2 + e3;
#pragma unroll
        for (int o = 16; o; o >>= 1) s += __shfl_xor_sync(0xffffffffu, s, o);

        const int t = bm + r;
        const size_t ob = (size_t)t * rowstride + headoff;
        outs[ob + lane]      = e0 / s;
        outs[ob + lane + 32] = e1 / s;
        outs[ob + lane + 64] = e2 / s;
        outs[ob + lane + 96] = e3 / s;

        float2 cs0 = g_rope[t * 64 + lane];
        float2 cs1 = g_rope[t * 64 + lane + 32];
        outr[ob + lane]      = f2tf(x0 * cs0.x - x2 * cs0.y);
        outr[ob + lane + 64] = f2tf(x2 * cs0.x + x0 * cs0.y);
        outr[ob + lane + 32] = f2tf(x1 * cs1.x - x3 * cs1.y);
        outr[ob + lane + 96] = f2tf(x3 * cs1.x + x1 * cs1.y);

        if (outg) {
            outg[ob + lane]      = (fminf(x0, 0.0f) - log1pf(expf(-fabsf(x0)))) * 0.0625f;
            outg[ob + lane + 32] = (fminf(x1, 0.0f) - log1pf(expf(-fabsf(x1)))) * 0.0625f;
            outg[ob + lane + 64] = (fminf(x2, 0.0f) - log1pf(expf(-fabsf(x2)))) * 0.0625f;
            outg[ob + lane + 96] = (fminf(x3, 0.0f) - log1pf(expf(-fabsf(x3)))) * 0.0625f;
        }
    }
}

// Merged q/k/v projections (fp16 mma) + fused prep.
__global__ void __launch_bounds__(256) proj_kernel()
{
    extern __shared__ unsigned smw[];
    const int bx = blockIdx.x, bm = blockIdx.y * 128;
    float acc[4][4][4];
    const int Kw = HIDN / 2;

    if (bx < 16) {
        gemm_f16_acc(smw, g_hsH, g_WqH, Kw, bm, bx * 128, acc);
        prep_epilogue(acc, smw, bm, HD, bx * DH, g_qs, g_sqT, nullptr);
    } else if (bx < 20) {
        const int kvh = bx - 16;
        gemm_f16_acc(smw, g_hsH, g_WkH, Kw, bm, kvh * 128, acc);
        prep_epilogue(acc, smw, bm, KVD, kvh * DH, g_ks, g_skT, g_gl);
    } else {
        gemm_f16_acc(smw, g_hsH, g_WvH, Kw, bm, (bx - 20) * 128, acc);
        gemm_store_v(acc, bm, (bx - 20) * 128);
    }
}

// Output projection (fp16 mma): out = cmb @ Wo^T(stored [N][K])
__global__ void __launch_bounds__(256) wo_kernel(float* __restrict__ out)
{
    extern __shared__ unsigned smw[];
    float acc[4][4][4];
    gemm_f16_acc(smw, g_cmbH, g_WoH, HD / 2, blockIdx.y * 128, blockIdx.x * 128, acc);
    gemm_store(acc, out, HIDN, blockIdx.y * 128, blockIdx.x * 128);
}

// =============================================================================
// GLA pass 1 (unchanged): grid (NCH, NKV, 2) — z selects a 64-wide d-half.
// =============================================================================
#define P1_SMEM ((64 * 68 * 2 + 64 * 132 + 64) * 4)

__global__ void __launch_bounds__(256) gla_pass1_kernel()
{
    extern __shared__ float sm1[];
    float* GL   = sm1;
    float* KW   = GL + 64 * 68;
    float* Vt   = KW + 64 * 68;
    float* LEND = Vt + 64 * 132;

    const int c = blockIdx.x, kvh = blockIdx.y, z = blockIdx.z;
    const int dbase = z * 64;
    const int tid = threadIdx.x;

    for (int i = tid; i < 64 * 64; i += 256) {
        int r = i >> 6, d = i & 63;
        GL[r * 68 + d] = g_gl[(c * CH + r) * KVD + kvh * DH + dbase + d];
    }
    for (int i = tid; i < 64 * 128; i += 256) {
        int r = i >> 7, d = i & 127;
        Vt[r * 132 + d] = g_v[(c * CH + r) * KVD + kvh * DH + d];
    }
    __syncthreads();

    if (tid < 64) {
        float cum = 0.0f;
#pragma unroll 4
        for (int t = 0; t < CH; t++) {
            cum += GL[t * 68 + tid];
            GL[t * 68 + tid] = expf(cum);
        }
        float le = GL[63 * 68 + tid];
        LEND[tid] = le;
        g_ltot[(kvh * NCH + c) * DH + dbase + tid] = le;
    }
    __syncthreads();

    for (int i = tid; i < 64 * 64; i += 256) {
        int r = i >> 6, d = i & 63;
        int gi = (c * CH + r) * KVD + kvh * DH + dbase + d;
        float lam = GL[r * 68 + d];
        float kdl = g_ks[gi] / lam;
        g_kdl[gi] = kdl;
        g_lam[gi] = lam;
        KW[r * 68 + d] = kdl * LEND[d];
    }
    __syncthreads();

    const int tx = tid & 15, ty = tid >> 4;
    float acc[4][8];
#pragma unroll
    for (int i = 0; i < 4; i++)
#pragma unroll
        for (int j = 0; j < 8; j++) acc[i][j] = 0.0f;

    for (int t = 0; t < CH; t++) {
        float a[4], b[8];
        *(float4*)&a[0] = *(const float4*)&KW[t * 68 + ty * 4];
        *(float4*)&b[0] = *(const float4*)&Vt[t * 132 + tx * 8];
        *(float4*)&b[4] = *(const float4*)&Vt[t * 132 + tx * 8 + 4];
#pragma unroll
        for (int i = 0; i < 4; i++)
#pragma unroll
            for (int j = 0; j < 8; j++) acc[i][j] += a[i] * b[j];
    }

    float* dS = g_dS + (size_t)(kvh * NCH + c) * DH * DH + (size_t)dbase * DH;
#pragma unroll
    for (int i = 0; i < 4; i++) {
        *(float4*)&dS[(ty * 4 + i) * DH + tx * 8]     = make_float4(acc[i][0], acc[i][1], acc[i][2], acc[i][3]);
        *(float4*)&dS[(ty * 4 + i) * DH + tx * 8 + 4] = make_float4(acc[i][4], acc[i][5], acc[i][6], acc[i][7]);
    }
}

// =============================================================================
// GLA pass 2 (unchanged)
// =============================================================================
__global__ void __launch_bounds__(128) gla_scan_kernel()
{
    const int kvh = blockIdx.x, d = blockIdx.y;
    const int dp = threadIdx.x;

    __shared__ float lt[NCH];
    if (dp < NCH) lt[dp] = g_ltot[(kvh * NCH + dp) * DH + d];
    __syncthreads();

    const size_t base = (size_t)(kvh * NCH) * DH * DH + (size_t)d * DH + dp;
    const float* __restrict__ src = g_dS + base;
    float* __restrict__ dst = g_S + base;
    const size_t step = (size_t)DH * DH;

    float s = 0.0f;
    float pre[4];
#pragma unroll
    for (int c = 0; c < 4; c++) pre[c] = src[c * step];
#pragma unroll
    for (int c = 0; c < NCH; c++) {
        float v = pre[c & 3];
        if (c + 4 < NCH) pre[c & 3] = src[(c + 4) * step];
        dst[c * step] = s;
        s = s * lt[c] + v;
    }
}

// =============================================================================
// GLA pass 3 (unchanged): writes 0.5*o_gla into g_gla.
// =============================================================================
__global__ void __launch_bounds__(512) gla_pass3_kernel()
{
    extern __shared__ float sm3[];
    float* QT = sm3;
    float* KT = QT + 128 * 65;
    float* Ss = KT + 128 * 65;
    float* Vs = Ss + 128 * 132;
    float* AT = Vs + 64 * 132;

    const int c = blockIdx.x, h = blockIdx.y;
    const int kvh = h >> 2;
    const int tid = threadIdx.x;

    for (int idx = tid; idx < CH * DH; idx += 512) {
        int r = idx >> 7, d = idx & 127;
        int kb = (c * CH + r) * KVD + kvh * DH + d;
        float lam = g_lam[kb];
        QT[d * 65 + r] = g_qs[(c * CH + r) * HD + h * DH + d] * lam;
        KT[d * 65 + r] = g_kdl[kb];
        Vs[r * 132 + d] = g_v[kb];
    }
    const float* Sg = g_S + (size_t)(kvh * NCH + c) * DH * DH;
    for (int idx = tid; idx < DH * DH; idx += 512) {
        int r = idx >> 7, d = idx & 127;
        Ss[r * 132 + d] = Sg[r * DH + d];
    }
    __syncthreads();

    const int tx = tid & 15, ty = tid >> 4;

    float O[2][8];
#pragma unroll
    for (int i = 0; i < 2; i++)
#pragma unroll
        for (int j = 0; j < 8; j++) O[i][j] = 0.0f;

    for (int dd = 0; dd < DH; dd++) {
        float a[2], b[8];
#pragma unroll
        for (int i = 0; i < 2; i++) a[i] = QT[dd * 65 + ty * 2 + i];
        *(float4*)&b[0] = *(const float4*)&Ss[dd * 132 + tx * 8];
        *(float4*)&b[4] = *(const float4*)&Ss[dd * 132 + tx * 8 + 4];
#pragma unroll
        for (int i = 0; i < 2; i++)
#pragma unroll
            for (int j = 0; j < 8; j++) O[i][j] += a[i] * b[j];
    }

    float Aacc[2][4];
#pragma unroll
    for (int i = 0; i < 2; i++)
#pragma unroll
        for (int j = 0; j < 4; j++) Aacc[i][j] = 0.0f;

    for (int dd = 0; dd < DH; dd++) {
        float a[2], b[4];
#pragma unroll
        for (int i = 0; i < 2; i++) a[i] = QT[dd * 65 + ty * 2 + i];
#pragma unroll
        for (int j = 0; j < 4; j++) b[j] = KT[dd * 65 + tx * 4 + j];
#pragma unroll
        for (int i = 0; i < 2; i++)
#pragma unroll
            for (int j = 0; j < 4; j++) Aacc[i][j] += a[i] * b[j];
    }
#pragma unroll
    for (int i = 0; i < 2; i++)
#pragma unroll
        for (int j = 0; j < 4; j++) {
            int t = ty * 2 + i, s = tx * 4 + j;
            AT[s * 65 + t] = (s <= t) ? Aacc[i][j] : 0.0f;
        }
    __syncthreads();

    for (int s = 0; s < CH; s++) {
        float a[2], b[8];
#pragma unroll
        for (int i = 0; i < 2; i++) a[i] = AT[s * 65 + ty * 2 + i];
        *(float4*)&b[0] = *(const float4*)&Vs[s * 132 + tx * 8];
        *(float4*)&b[4] = *(const float4*)&Vs[s * 132 + tx * 8 + 4];
#pragma unroll
        for (int i = 0; i < 2; i++)
#pragma unroll
            for (int j = 0; j < 8; j++) O[i][j] += a[i] * b[j];
    }

#pragma unroll
    for (int i = 0; i < 2; i++) {
        int t = c * CH + ty * 2 + i;
        float4 o0 = make_float4(0.5f*O[i][0], 0.5f*O[i][1], 0.5f*O[i][2], 0.5f*O[i][3]);
        float4 o1 = make_float4(0.5f*O[i][4], 0.5f*O[i][5], 0.5f*O[i][6], 0.5f*O[i][7]);
        *(float4*)&g_gla[t * HD + h * DH + tx * 8]     = o0;
        *(float4*)&g_gla[t * HD + h * DH + tx * 8 + 4] = o1;
    }
}

// =============================================================================
// Causal flash attention (unchanged tf32 path): writes 0.5*y into g_y.
// =============================================================================
#define ATTN_SMEM ((128*132 + 2*64*132 + 64*136 + 8*16*68) * 4)   // 204800 B

__global__ void __launch_bounds__(256) attn_tc_kernel()
{
    extern __shared__ char smraw[];
    unsigned* Qs = (unsigned*)smraw;
    unsigned* Ks = (unsigned*)(smraw + 128 * 132 * 4);
    unsigned* Vs = (unsigned*)(smraw + (128 * 132 + 2 * 64 * 132) * 4);
    unsigned* Pb = (unsigned*)(smraw + (128 * 132 + 2 * 64 * 132 + 64 * 136) * 4);

    const int qt = gridDim.x - 1 - blockIdx.x;
    const int h = blockIdx.y;
    const int kvh = h >> 2;
    const int tid = threadIdx.x;
    const int warp = tid >> 5, lane = tid & 31;
    const int gid = lane >> 2, tig = lane & 3;
    unsigned* Pw = Pb + warp * 16 * 68;
    const float scale = 0.08838834764831845f;
    const int ktmax = 2 * qt + 1;

    {
#pragma unroll
        for (int i = 0; i < 8; i++) {
            int idx = tid + i * 256;
            int r = idx >> 5, c4 = (idx & 31) * 4;
            cp16(&Ks[r * 132 + c4], &g_skT[(size_t)r * KVD + kvh * DH + c4]);
        }
        asm volatile("cp.async.commit_group;");
    }

    for (int i = tid; i < 128 * 32; i += 256) {
        int r = i >> 5, c4 = (i & 31) * 4;
        *(uint4*)&Qs[r * 132 + c4] =
            *(const uint4*)&g_sqT[(size_t)(qt * 128 + r) * HD + h * DH + c4];
    }

    const int rbase = qt * 128 + warp * 16;
    float m_i[2] = {-1e30f, -1e30f};
    float l_i[2] = {0.0f, 0.0f};
    float c[16][4];
#pragma unroll
    for (int ni = 0; ni < 16; ni++)
#pragma unroll
        for (int v = 0; v < 4; v++) c[ni][v] = 0.0f;

    for (int kt = 0; kt <= ktmax; kt++) {
        __syncthreads();

#pragma unroll
        for (int i = 0; i < 8; i++) {
            int idx = tid + i * 256;
            int r = idx >> 5, c4 = (idx & 31) * 4;
            cp16(&Vs[r * 136 + c4], &g_vT[(size_t)(kt * 64 + r) * KVD + kvh * DH + c4]);
        }
        asm volatile("cp.async.commit_group;");

        {
            const int ktn = (kt < ktmax) ? kt + 1 : kt;
            unsigned* KB = Ks + ((kt + 1) & 1) * 64 * 132;
#pragma unroll
            for (int i = 0; i < 8; i++) {
                int idx = tid + i * 256;
                int r = idx >> 5, c4 = (idx & 31) * 4;
                cp16(&KB[r * 132 + c4], &g_skT[(size_t)(ktn * 64 + r) * KVD + kvh * DH + c4]);
            }
            asm volatile("cp.async.commit_group;");
        }

        asm volatile("cp.async.wait_group 2;");
        __syncthreads();

        const unsigned* KB = Ks + (kt & 1) * 64 * 132;
        const int smin = kt * 64;
        const bool active = (smin <= rbase + 15);

        if (active) {
            float sacc[8][4];
#pragma unroll
            for (int ni = 0; ni < 8; ni++)
#pragma unroll
                for (int v = 0; v < 4; v++) sacc[ni][v] = 0.0f;

#pragma unroll 4
            for (int k8 = 0; k8 < 16; k8++) {
                unsigned aq[4];
                int qr = warp * 16 + gid;
                aq[0] = Qs[qr * 132 + k8 * 8 + tig];
                aq[1] = Qs[(qr + 8) * 132 + k8 * 8 + tig];
                aq[2] = Qs[qr * 132 + k8 * 8 + tig + 4];
                aq[3] = Qs[(qr + 8) * 132 + k8 * 8 + tig + 4];
#pragma unroll
                for (int ni = 0; ni < 8; ni++) {
                    unsigned b0 = KB[(ni * 8 + gid) * 132 + k8 * 8 + tig];
                    unsigned b1 = KB[(ni * 8 + gid) * 132 + k8 * 8 + tig + 4];
                    mma_tf32(sacc[ni], aq, b0, b1);
                }
            }

            const bool partial = (smin + 63 > rbase);
#pragma unroll
            for (int ni = 0; ni < 8; ni++)
#pragma unroll
                for (int v = 0; v < 4; v++) {
                    float sv = sacc[ni][v] * scale;
                    if (partial) {
                        int row = rbase + gid + (v >> 1) * 8;
                        int col = smin + ni * 8 + tig * 2 + (v & 1);
                        if (col > row) sv = -1e30f;
                    }
                    sacc[ni][v] = sv;
                }

#pragma unroll
            for (int h2 = 0; h2 < 2; h2++) {
                float rmax = -1e30f;
#pragma unroll
                for (int ni = 0; ni < 8; ni++)
                    rmax = fmaxf(rmax, fmaxf(sacc[ni][2 * h2], sacc[ni][2 * h2 + 1]));
                rmax = fmaxf(rmax, __shfl_xor_sync(0xffffffffu, rmax, 1));
                rmax = fmaxf(rmax, __shfl_xor_sync(0xffffffffu, rmax, 2));
                float mnew = fmaxf(m_i[h2], rmax);
                float alpha = __expf(m_i[h2] - mnew);
                float rsum = 0.0f;
#pragma unroll
                for (int ni = 0; ni < 8; ni++) {
                    float p0 = __expf(sacc[ni][2 * h2] - mnew);
                    float p1 = __expf(sacc[ni][2 * h2 + 1] - mnew);
                    sacc[ni][2 * h2] = p0;
                    sacc[ni][2 * h2 + 1] = p1;
                    rsum += p0 + p1;
                }
                rsum += __shfl_xor_sync(0xffffffffu, rsum, 1);
                rsum += __shfl_xor_sync(0xffffffffu, rsum, 2);
                l_i[h2] = l_i[h2] * alpha + rsum;
                m_i[h2] = mnew;
#pragma unroll
                for (int ni = 0; ni < 16; ni++) {
                    c[ni][2 * h2]     *= alpha;
                    c[ni][2 * h2 + 1] *= alpha;
                }
            }

#pragma unroll
            for (int ni = 0; ni < 8; ni++) {
                *(uint2*)&Pw[gid * 68 + ni * 8 + tig * 2] =
                    make_uint2(f2tf(sacc[ni][0]), f2tf(sacc[ni][1]));
                *(uint2*)&Pw[(gid + 8) * 68 + ni * 8 + tig * 2] =
                    make_uint2(f2tf(sacc[ni][2]), f2tf(sacc[ni][3]));
            }
        }

        asm volatile("cp.async.wait_group 1;");
        __syncthreads();

        if (active) {
#pragma unroll 2
            for (int k8 = 0; k8 < 8; k8++) {
                unsigned ap[4];
                ap[0] = Pw[gid * 68 + k8 * 8 + tig];
                ap[1] = Pw[(gid + 8) * 68 + k8 * 8 + tig];
                ap[2] = Pw[gid * 68 + k8 * 8 + tig + 4];
                ap[3] = Pw[(gid + 8) * 68 + k8 * 8 + tig + 4];
#pragma unroll
                for (int ni = 0; ni < 16; ni++) {
                    unsigned b0 = Vs[(k8 * 8 + tig) * 136 + ni * 8 + gid];
                    unsigned b1 = Vs[(k8 * 8 + tig + 4) * 136 + ni * 8 + gid];
                    mma_tf32(c[ni], ap, b0, b1);
                }
            }
        }
    }

    const float h0 = 0.5f / l_i[0];
    const float h1 = 0.5f / l_i[1];
    const int r0 = rbase + gid, r1 = r0 + 8;
#pragma unroll
    for (int ni = 0; ni < 16; ni++) {
        int col = h * DH + ni * 8 + tig * 2;
        *(float2*)&g_y[(size_t)r0 * HD + col] = make_float2(c[ni][0] * h0, c[ni][1] * h0);
        *(float2*)&g_y[(size_t)r1 * HD + col] = make_float2(c[ni][2] * h1, c[ni][3] * h1);
    }
}

// =============================================================================
// host launcher — fork/join: GLA chain (stream A) || attention (stream B)
// =============================================================================
extern "C" void kernel_launch(void* const* d_in, const int* in_sizes, int n_in,
                              void* d_out, int out_size)
{
    (void)in_sizes; (void)n_in; (void)out_size;
    const float* hs = (const float*)d_in[0];
    const float* Wq = (const float*)d_in[1];
    const float* Wk = (const float*)d_in[2];
    const float* Wv = (const float*)d_in[3];
    const float* Wo = (const float*)d_in[4];
    float* out = (float*)d_out;

    unsigned *p_hsH, *p_WqH, *p_WkH, *p_WvH, *p_WoH;
    cudaGetSymbolAddress((void**)&p_hsH, g_hsH);
    cudaGetSymbolAddress((void**)&p_WqH, g_WqH);
    cudaGetSymbolAddress((void**)&p_WkH, g_WkH);
    cudaGetSymbolAddress((void**)&p_WvH, g_WvH);
    cudaGetSymbolAddress((void**)&p_WoH, g_WoH);

    static cudaStream_t sA = nullptr, sB = nullptr;
    static cudaEvent_t ev0, evP, evA, evB;
    if (sA == nullptr) {
        cudaStreamCreateWithFlags(&sA, cudaStreamNonBlocking);
        cudaStreamCreateWithFlags(&sB, cudaStreamNonBlocking);
        cudaEventCreateWithFlags(&ev0, cudaEventDisableTiming);
        cudaEventCreateWithFlags(&evP, cudaEventDisableTiming);
        cudaEventCreateWithFlags(&evA, cudaEventDisableTiming);
        cudaEventCreateWithFlags(&evB, cudaEventDisableTiming);
    }

    const int smem3 = (2 * 128 * 65 + 128 * 132 + 64 * 132 + 64 * 65) * 4;
    cudaFuncSetAttribute(proj_kernel,      cudaFuncAttributeMaxDynamicSharedMemorySize, GEMM_SMEM);
    cudaFuncSetAttribute(wo_kernel,        cudaFuncAttributeMaxDynamicSharedMemorySize, GEMM_SMEM);
    cudaFuncSetAttribute(gla_pass1_kernel, cudaFuncAttributeMaxDynamicSharedMemorySize, P1_SMEM);
    cudaFuncSetAttribute(gla_pass3_kernel, cudaFuncAttributeMaxDynamicSharedMemorySize, smem3);
    cudaFuncSetAttribute(attn_tc_kernel,   cudaFuncAttributeMaxDynamicSharedMemorySize, ATTN_SMEM);

    // --- fork Wo transpose+pack onto stream A early (only wo needs it) ---
    cudaEventRecord(ev0, 0);
    cudaStreamWaitEvent(sA, ev0, 0);
    transpose_cvt_h_kernel<<<dim3(HIDN / 32, HD / 32), 256, 0, sA>>>(
        Wo, (__half*)p_WoH, HD, HIDN);

    // --- main stream: rope + hs pack + weight transposes + projections ---
    rope_table_kernel<<<NTOK, 64>>>();
    cvt_h_kernel<<<4096, 256>>>((const float4*)hs, (uint2*)p_hsH, NTOK * HIDN / 4);
    transpose_cvt_h_kernel<<<dim3(HD / 32,  HIDN / 32), 256>>>(Wq, (__half*)p_WqH, HIDN, HD);
    transpose_cvt_h_kernel<<<dim3(KVD / 32, HIDN / 32), 256>>>(Wk, (__half*)p_WkH, HIDN, KVD);
    transpose_cvt_h_kernel<<<dim3(KVD / 32, HIDN / 32), 256>>>(Wv, (__half*)p_WvH, HIDN, KVD);
    proj_kernel<<<dim3(24, 16), 256, GEMM_SMEM>>>();
    cudaEventRecord(evP, 0);

    // --- stream A: GLA chain ---
    cudaStreamWaitEvent(sA, evP, 0);
    gla_pass1_kernel<<<dim3(NCH, NKV, 2), 256, P1_SMEM, sA>>>();
    gla_scan_kernel<<<dim3(NKV, DH), 128, 0, sA>>>();
    gla_pass3_kernel<<<dim3(NCH, NH), 512, smem3, sA>>>();
    cudaEventRecord(evA, sA);

    // --- stream B: causal flash attention (concurrent with GLA chain) ---
    cudaStreamWaitEvent(sB, evP, 0);
    attn_tc_kernel<<<dim3(NTOK / 128, NH), 256, ATTN_SMEM, sB>>>();
    cudaEventRecord(evB, sB);

    // --- join, combine, output projection ---
    cudaStreamWaitEvent(0, evA, 0);
    cudaStreamWaitEvent(0, evB, 0);
    combine_kernel<<<NTOK * HD / 4 / 256, 256>>>();
    wo_kernel<<<dim3(16, 16), 256, GEMM_SMEM>>>(out);
}

// round 17
// speedup vs baseline: 1.5465x; 1.1482x over previous
#include <cuda_runtime.h>
#include <cuda_fp16.h>
#include <math.h>

// Problem constants
#define NTOK 2048
#define HIDN 2048
#define NH   16
#define NKV  4
#define DH   128
#define HD   (NH*DH)     // 2048
#define KVD  (NKV*DH)    // 512
#define CH   64
#define NCH  (NTOK/CH)   // 32

// ---------------- scratch (static device globals; no allocation) -------------
__device__ __half   g_sqH [NTOK*HD];      // roped q, fp16 (attn)
__device__ float    g_qs  [NTOK*HD];      // softmax q (GLA)
__device__ __half   g_skH [NTOK*KVD];     // roped k, fp16 (attn)
__device__ float    g_ks  [NTOK*KVD];     // softmax k (GLA)
__device__ float    g_gl  [NTOK*KVD];
__device__ float    g_v   [NTOK*KVD];     // fp32 v (GLA)
__device__ __half   g_vHT [NKV*DH*NTOK];  // fp16 v TRANSPOSED [kvh][d][s] (attn)
__device__ float    g_lam [NTOK*KVD];
__device__ float    g_kdl [NTOK*KVD];
__device__ float    g_dS  [NKV*NCH*DH*DH];
__device__ float    g_S   [NKV*NCH*DH*DH];
__device__ float    g_ltot[NKV*NCH*DH];
__device__ float    g_y   [NTOK*HD];      // 0.5 * attention branch
__device__ float    g_gla [NTOK*HD];      // 0.5 * GLA branch
__device__ float2   g_rope[NTOK*64];
// fp16 GEMM operands (packed half2 words). Weights TRANSPOSED to [N][K].
__device__ unsigned g_hsH [NTOK*HIDN/2];
__device__ unsigned g_WqH [HD*HIDN/2];
__device__ unsigned g_WkH [KVD*HIDN/2];
__device__ unsigned g_WvH [KVD*HIDN/2];
__device__ unsigned g_WoH [HIDN*HD/2];
__device__ unsigned g_cmbH[NTOK*HD/2];

// ---------------- helpers ----------------------------------------------------
__device__ __forceinline__ unsigned f2h2(float a, float b) {
    __half2 h = __floats2half2_rn(a, b);
    return *(unsigned*)&h;
}

// fp16 mma: m16n8k16, fp32 accumulate
__device__ __forceinline__ void mma_f16(float c[4], const unsigned a[4],
                                        unsigned b0, unsigned b1) {
    asm volatile(
        "mma.sync.aligned.m16n8k16.row.col.f32.f16.f16.f32 "
        "{%0,%1,%2,%3}, {%4,%5,%6,%7}, {%8,%9}, {%0,%1,%2,%3};"
        : "+f"(c[0]), "+f"(c[1]), "+f"(c[2]), "+f"(c[3])
        : "r"(a[0]), "r"(a[1]), "r"(a[2]), "r"(a[3]), "r"(b0), "r"(b1));
}

__device__ __forceinline__ void cp16(void* dst, const void* src) {
    unsigned d = (unsigned)__cvta_generic_to_shared(dst);
    asm volatile("cp.async.cg.shared.global [%0], [%1], 16;" :: "r"(d), "l"(src));
}

// =============================================================================
// fp32 -> fp16 packing (hs) and transpose+pack (weights -> [N][K])
// =============================================================================
__global__ void __launch_bounds__(256) cvt_h_kernel(
    const float4* __restrict__ src, uint2* __restrict__ dst, int n4)
{
    int i = blockIdx.x * blockDim.x + threadIdx.x;
    if (i < n4) {
        float4 v = src[i];
        dst[i] = make_uint2(f2h2(v.x, v.y), f2h2(v.z, v.w));
    }
}

__global__ void __launch_bounds__(256) transpose_cvt_h_kernel(
    const float* __restrict__ src, __half* __restrict__ dst, int K, int N)
{
    __shared__ float tile[32][33];
    const int n0 = blockIdx.x * 32, k0 = blockIdx.y * 32;
    const int tx = threadIdx.x & 31, ty = threadIdx.x >> 5;
#pragma unroll
    for (int p = 0; p < 4; p++)
        tile[ty + p * 8][tx] = src[(size_t)(k0 + ty + p * 8) * N + n0 + tx];
    __syncthreads();
#pragma unroll
    for (int p = 0; p < 4; p++)
        dst[(size_t)(n0 + ty + p * 8) * K + k0 + tx] = __float2half_rn(tile[tx][ty + p * 8]);
}

// V transpose: g_v [t][kvh*DH + d] fp32 -> g_vHT [kvh][d][t] fp16
__global__ void __launch_bounds__(256) transpose_vh_kernel()
{
    __shared__ float tile[32][33];
    const int t0 = blockIdx.x * 32, d0 = blockIdx.y * 32, kvh = blockIdx.z;
    const int tx = threadIdx.x & 31, ty = threadIdx.x >> 5;
#pragma unroll
    for (int p = 0; p < 4; p++)
        tile[ty + p * 8][tx] = g_v[(size_t)(t0 + ty + p * 8) * KVD + kvh * DH + d0 + tx];
    __syncthreads();
#pragma unroll
    for (int p = 0; p < 4; p++)
        g_vHT[(size_t)(kvh * DH + d0 + ty + p * 8) * NTOK + t0 + tx] =
            __float2half_rn(tile[tx][ty + p * 8]);
}

// combine: cmbH = fp16(y + gla)
__global__ void __launch_bounds__(256) combine_kernel()
{
    int i = blockIdx.x * blockDim.x + threadIdx.x;
    float4 a = ((const float4*)g_y)[i];
    float4 b = ((const float4*)g_gla)[i];
    ((uint2*)g_cmbH)[i] = make_uint2(f2h2(a.x + b.x, a.y + b.y),
                                     f2h2(a.z + b.z, a.w + b.w));
}

// =============================================================================
// RoPE cos/sin table
// =============================================================================
__global__ void __launch_bounds__(64) rope_table_kernel()
{
    const int t = blockIdx.x, j = threadIdx.x;
    float inv_freq = (float)pow(10000.0, -(double)(2 * j) / 128.0);
    float fr = (float)t * inv_freq;
    double ang = (double)fr;
    g_rope[t * 64 + j] = make_float2((float)cos(ang), (float)sin(ang));
}

// =============================================================================
// FP16 GEMM v6 (unchanged from R14)
// =============================================================================
#define ASW 20
#define ABUFW (128 * ASW)
#define GEMM_SMEM (128 * 132 * 4)

__device__ __forceinline__ void gemm_issue_h(
    unsigned* As, unsigned* Bs,
    const unsigned* __restrict__ A, const unsigned* __restrict__ B,
    int Kw, int bm, int bn, int k0w)
{
    const int t = threadIdx.x;
    const int r = t >> 1, h8 = (t & 1) * 8;
    {
        const unsigned* src = &A[(size_t)(bm + r) * Kw + k0w + h8];
        unsigned* dst = &As[r * ASW + h8];
        cp16(dst, src);
        cp16(dst + 4, src + 4);
    }
    {
        const unsigned* src = &B[(size_t)(bn + r) * Kw + k0w + h8];
        unsigned* dst = &Bs[r * ASW + h8];
        cp16(dst, src);
        cp16(dst + 4, src + 4);
    }
}

__device__ __forceinline__ void gemm_f16_acc(
    unsigned* __restrict__ smw,
    const unsigned* __restrict__ A, const unsigned* __restrict__ B,
    int Kw, int bm, int bn, float acc[4][4][4])
{
    unsigned* As = smw;
    unsigned* Bs = smw + 2 * ABUFW;

    const int tid  = threadIdx.x;
    const int warp = tid >> 5, lane = tid & 31;
    const int gid  = lane >> 2, tig = lane & 3;
    const int wm   = (warp & 1) * 64, wn = (warp >> 1) * 32;

#pragma unroll
    for (int mi = 0; mi < 4; mi++)
#pragma unroll
        for (int ni = 0; ni < 4; ni++)
#pragma unroll
            for (int v = 0; v < 4; v++) acc[mi][ni][v] = 0.0f;

    const int nIter = Kw >> 4;
    gemm_issue_h(As, Bs, A, B, Kw, bm, bn, 0);
    asm volatile("cp.async.commit_group;");
    if (nIter > 1) {
        gemm_issue_h(As + ABUFW, Bs + ABUFW, A, B, Kw, bm, bn, 16);
    }
    asm volatile("cp.async.commit_group;");

    for (int it = 0; it < nIter; it++) {
        if (it + 1 < nIter)
            asm volatile("cp.async.wait_group 1;");
        else
            asm volatile("cp.async.wait_group 0;");
        __syncthreads();

        const unsigned* as = As + (it & 1) * ABUFW;
        const unsigned* bs = Bs + (it & 1) * ABUFW;
#pragma unroll
        for (int step = 0; step < 2; step++) {
            unsigned af[4][4];
#pragma unroll
            for (int mi = 0; mi < 4; mi++) {
                int r = wm + mi * 16 + gid;
                af[mi][0] = as[r * ASW + step * 8 + tig];
                af[mi][1] = as[(r + 8) * ASW + step * 8 + tig];
                af[mi][2] = as[r * ASW + step * 8 + tig + 4];
                af[mi][3] = as[(r + 8) * ASW + step * 8 + tig + 4];
            }
#pragma unroll
            for (int ni = 0; ni < 4; ni++) {
                unsigned b0 = bs[(wn + ni * 8 + gid) * ASW + step * 8 + tig];
                unsigned b1 = bs[(wn + ni * 8 + gid) * ASW + step * 8 + tig + 4];
#pragma unroll
                for (int mi = 0; mi < 4; mi++) mma_f16(acc[mi][ni], af[mi], b0, b1);
            }
        }
        __syncthreads();

        if (it + 2 < nIter) {
            gemm_issue_h(As + (it & 1) * ABUFW, Bs + (it & 1) * ABUFW,
                         A, B, Kw, bm, bn, (it + 2) * 16);
        }
        asm volatile("cp.async.commit_group;");
    }
}

__device__ __forceinline__ void gemm_store(
    float acc[4][4][4], float* __restrict__ C, int N, int bm, int bn)
{
    const int tid  = threadIdx.x;
    const int warp = tid >> 5, lane = tid & 31;
    const int gid  = lane >> 2, tig = lane & 3;
    const int wm   = (warp & 1) * 64, wn = (warp >> 1) * 32;
#pragma unroll
    for (int mi = 0; mi < 4; mi++) {
        int r0 = bm + wm + mi * 16 + gid;
#pragma unroll
        for (int ni = 0; ni < 4; ni++) {
            int col = bn + wn + ni * 8 + tig * 2;
            *(float2*)&C[(size_t)r0 * N + col]       = make_float2(acc[mi][ni][0], acc[mi][ni][1]);
            *(float2*)&C[(size_t)(r0 + 8) * N + col] = make_float2(acc[mi][ni][2], acc[mi][ni][3]);
        }
    }
}

// Fused prep epilogue: softmax -> outs (fp32), RoPE -> outr (fp16),
// optional logsigmoid/16 -> outg.
__device__ __forceinline__ void prep_epilogue(
    float acc[4][4][4], unsigned* smw, int bm, int rowstride, int headoff,
    float* __restrict__ outs, __half* __restrict__ outr, float* __restrict__ outg)
{
    float* St = (float*)smw;   // [128][132]
    const int tid  = threadIdx.x;
    const int warp = tid >> 5, lane = tid & 31;
    const int gid  = lane >> 2, tig = lane & 3;
    const int wm   = (warp & 1) * 64, wn = (warp >> 1) * 32;

#pragma unroll
    for (int mi = 0; mi < 4; mi++) {
        int r0 = wm + mi * 16 + gid;
#pragma unroll
        for (int ni = 0; ni < 4; ni++) {
            int col = wn + ni * 8 + tig * 2;
            *(float2*)&St[r0 * 132 + col]       = make_float2(acc[mi][ni][0], acc[mi][ni][1]);
            *(float2*)&St[(r0 + 8) * 132 + col] = make_float2(acc[mi][ni][2], acc[mi][ni][3]);
        }
    }
    __syncthreads();

    for (int r = warp; r < 128; r += 8) {
        const float* Sr = St + r * 132;
        float x0 = Sr[lane], x1 = Sr[lane + 32], x2 = Sr[lane + 64], x3 = Sr[lane + 96];

        float m = fmaxf(fmaxf(x0, x1), fmaxf(x2, x3));
#pragma unroll
        for (int o = 16; o; o >>= 1) m = fmaxf(m, __shfl_xor_sync(0xffffffffu, m, o));

        float e0 = expf(x0 - m), e1 = expf(x1 - m), e2 = expf(x2 - m), e3 = expf(x3 - m);
        float s = e0 + e1 + e2 + e3;
#pragma unroll
        for (int o = 16; o; o >>= 1) s += __shfl_xor_sync(0xffffffffu, s, o);

        const int t = bm + r;
        const size_t ob = (size_t)t * rowstride + headoff;
        outs[ob + lane]      = e0 / s;
        outs[ob + lane + 32] = e1 / s;
        outs[ob + lane + 64] = e2 / s;
        outs[ob + lane + 96] = e3 / s;

        float2 cs0 = g_rope[t * 64 + lane];
        float2 cs1 = g_rope[t * 64 + lane + 32];
        outr[ob + lane]      = __float2half_rn(x0 * cs0.x - x2 * cs0.y);
        outr[ob + lane + 64] = __float2half_rn(x2 * cs0.x + x0 * cs0.y);
        outr[ob + lane + 32] = __float2half_rn(x1 * cs1.x - x3 * cs1.y);
        outr[ob + lane + 96] = __float2half_rn(x3 * cs1.x + x1 * cs1.y);

        if (outg) {
            outg[ob + lane]      = (fminf(x0, 0.0f) - log1pf(expf(-fabsf(x0)))) * 0.0625f;
            outg[ob + lane + 32] = (fminf(x1, 0.0f) - log1pf(expf(-fabsf(x1)))) * 0.0625f;
            outg[ob + lane + 64] = (fminf(x2, 0.0f) - log1pf(expf(-fabsf(x2)))) * 0.0625f;
            outg[ob + lane + 96] = (fminf(x3, 0.0f) - log1pf(expf(-fabsf(x3)))) * 0.0625f;
        }
    }
}

// Merged q/k/v projections (fp16 mma) + fused prep.
__global__ void __launch_bounds__(256) proj_kernel()
{
    extern __shared__ unsigned smw[];
    const int bx = blockIdx.x, bm = blockIdx.y * 128;
    float acc[4][4][4];
    const int Kw = HIDN / 2;

    if (bx < 16) {
        gemm_f16_acc(smw, g_hsH, g_WqH, Kw, bm, bx * 128, acc);
        prep_epilogue(acc, smw, bm, HD, bx * DH, g_qs, g_sqH, nullptr);
    } else if (bx < 20) {
        const int kvh = bx - 16;
        gemm_f16_acc(smw, g_hsH, g_WkH, Kw, bm, kvh * 128, acc);
        prep_epilogue(acc, smw, bm, KVD, kvh * DH, g_ks, g_skH, g_gl);
    } else {
        gemm_f16_acc(smw, g_hsH, g_WvH, Kw, bm, (bx - 20) * 128, acc);
        gemm_store(acc, g_v, KVD, bm, (bx - 20) * 128);
    }
}

// Output projection (fp16 mma)
__global__ void __launch_bounds__(256) wo_kernel(float* __restrict__ out)
{
    extern __shared__ unsigned smw[];
    float acc[4][4][4];
    gemm_f16_acc(smw, g_cmbH, g_WoH, HD / 2, blockIdx.y * 128, blockIdx.x * 128, acc);
    gemm_store(acc, out, HIDN, blockIdx.y * 128, blockIdx.x * 128);
}

// =============================================================================
// GLA pass 1 (unchanged)
// =============================================================================
#define P1_SMEM ((64 * 68 * 2 + 64 * 132 + 64) * 4)

__global__ void __launch_bounds__(256) gla_pass1_kernel()
{
    extern __shared__ float sm1[];
    float* GL   = sm1;
    float* KW   = GL + 64 * 68;
    float* Vt   = KW + 64 * 68;
    float* LEND = Vt + 64 * 132;

    const int c = blockIdx.x, kvh = blockIdx.y, z = blockIdx.z;
    const int dbase = z * 64;
    const int tid = threadIdx.x;

    for (int i = tid; i < 64 * 64; i += 256) {
        int r = i >> 6, d = i & 63;
        GL[r * 68 + d] = g_gl[(c * CH + r) * KVD + kvh * DH + dbase + d];
    }
    for (int i = tid; i < 64 * 128; i += 256) {
        int r = i >> 7, d = i & 127;
        Vt[r * 132 + d] = g_v[(c * CH + r) * KVD + kvh * DH + d];
    }
    __syncthreads();

    if (tid < 64) {
        float cum = 0.0f;
#pragma unroll 4
        for (int t = 0; t < CH; t++) {
            cum += GL[t * 68 + tid];
            GL[t * 68 + tid] = expf(cum);
        }
        float le = GL[63 * 68 + tid];
        LEND[tid] = le;
        g_ltot[(kvh * NCH + c) * DH + dbase + tid] = le;
    }
    __syncthreads();

    for (int i = tid; i < 64 * 64; i += 256) {
        int r = i >> 6, d = i & 63;
        int gi = (c * CH + r) * KVD + kvh * DH + dbase + d;
        float lam = GL[r * 68 + d];
        float kdl = g_ks[gi] / lam;
        g_kdl[gi] = kdl;
        g_lam[gi] = lam;
        KW[r * 68 + d] = kdl * LEND[d];
    }
    __syncthreads();

    const int tx = tid & 15, ty = tid >> 4;
    float acc[4][8];
#pragma unroll
    for (int i = 0; i < 4; i++)
#pragma unroll
        for (int j = 0; j < 8; j++) acc[i][j] = 0.0f;

    for (int t = 0; t < CH; t++) {
        float a[4], b[8];
        *(float4*)&a[0] = *(const float4*)&KW[t * 68 + ty * 4];
        *(float4*)&b[0] = *(const float4*)&Vt[t * 132 + tx * 8];
        *(float4*)&b[4] = *(const float4*)&Vt[t * 132 + tx * 8 + 4];
#pragma unroll
        for (int i = 0; i < 4; i++)
#pragma unroll
            for (int j = 0; j < 8; j++) acc[i][j] += a[i] * b[j];
    }

    float* dS = g_dS + (size_t)(kvh * NCH + c) * DH * DH + (size_t)dbase * DH;
#pragma unroll
    for (int i = 0; i < 4; i++) {
        *(float4*)&dS[(ty * 4 + i) * DH + tx * 8]     = make_float4(acc[i][0], acc[i][1], acc[i][2], acc[i][3]);
        *(float4*)&dS[(ty * 4 + i) * DH + tx * 8 + 4] = make_float4(acc[i][4], acc[i][5], acc[i][6], acc[i][7]);
    }
}

// =============================================================================
// GLA pass 2 (unchanged)
// =============================================================================
__global__ void __launch_bounds__(128) gla_scan_kernel()
{
    const int kvh = blockIdx.x, d = blockIdx.y;
    const int dp = threadIdx.x;

    __shared__ float lt[NCH];
    if (dp < NCH) lt[dp] = g_ltot[(kvh * NCH + dp) * DH + d];
    __syncthreads();

    const size_t base = (size_t)(kvh * NCH) * DH * DH + (size_t)d * DH + dp;
    const float* __restrict__ src = g_dS + base;
    float* __restrict__ dst = g_S + base;
    const size_t step = (size_t)DH * DH;

    float s = 0.0f;
    float pre[4];
#pragma unroll
    for (int c = 0; c < 4; c++) pre[c] = src[c * step];
#pragma unroll
    for (int c = 0; c < NCH; c++) {
        float v = pre[c & 3];
        if (c + 4 < NCH) pre[c & 3] = src[(c + 4) * step];
        dst[c * step] = s;
        s = s * lt[c] + v;
    }
}

// =============================================================================
// GLA pass 3 (unchanged): writes 0.5*o_gla into g_gla.
// =============================================================================
__global__ void __launch_bounds__(512) gla_pass3_kernel()
{
    extern __shared__ float sm3[];
    float* QT = sm3;
    float* KT = QT + 128 * 65;
    float* Ss = KT + 128 * 65;
    float* Vs = Ss + 128 * 132;
    float* AT = Vs + 64 * 132;

    const int c = blockIdx.x, h = blockIdx.y;
    const int kvh = h >> 2;
    const int tid = threadIdx.x;

    for (int idx = tid; idx < CH * DH; idx += 512) {
        int r = idx >> 7, d = idx & 127;
        int kb = (c * CH + r) * KVD + kvh * DH + d;
        float lam = g_lam[kb];
        QT[d * 65 + r] = g_qs[(c * CH + r) * HD + h * DH + d] * lam;
        KT[d * 65 + r] = g_kdl[kb];
        Vs[r * 132 + d] = g_v[kb];
    }
    const float* Sg = g_S + (size_t)(kvh * NCH + c) * DH * DH;
    for (int idx = tid; idx < DH * DH; idx += 512) {
        int r = idx >> 7, d = idx & 127;
        Ss[r * 132 + d] = Sg[r * DH + d];
    }
    __syncthreads();

    const int tx = tid & 15, ty = tid >> 4;

    float O[2][8];
#pragma unroll
    for (int i = 0; i < 2; i++)
#pragma unroll
        for (int j = 0; j < 8; j++) O[i][j] = 0.0f;

    for (int dd = 0; dd < DH; dd++) {
        float a[2], b[8];
#pragma unroll
        for (int i = 0; i < 2; i++) a[i] = QT[dd * 65 + ty * 2 + i];
        *(float4*)&b[0] = *(const float4*)&Ss[dd * 132 + tx * 8];
        *(float4*)&b[4] = *(const float4*)&Ss[dd * 132 + tx * 8 + 4];
#pragma unroll
        for (int i = 0; i < 2; i++)
#pragma unroll
            for (int j = 0; j < 8; j++) O[i][j] += a[i] * b[j];
    }

    float Aacc[2][4];
#pragma unroll
    for (int i = 0; i < 2; i++)
#pragma unroll
        for (int j = 0; j < 4; j++) Aacc[i][j] = 0.0f;

    for (int dd = 0; dd < DH; dd++) {
        float a[2], b[4];
#pragma unroll
        for (int i = 0; i < 2; i++) a[i] = QT[dd * 65 + ty * 2 + i];
#pragma unroll
        for (int j = 0; j < 4; j++) b[j] = KT[dd * 65 + tx * 4 + j];
#pragma unroll
        for (int i = 0; i < 2; i++)
#pragma unroll
            for (int j = 0; j < 4; j++) Aacc[i][j] += a[i] * b[j];
    }
#pragma unroll
    for (int i = 0; i < 2; i++)
#pragma unroll
        for (int j = 0; j < 4; j++) {
            int t = ty * 2 + i, s = tx * 4 + j;
            AT[s * 65 + t] = (s <= t) ? Aacc[i][j] : 0.0f;
        }
    __syncthreads();

    for (int s = 0; s < CH; s++) {
        float a[2], b[8];
#pragma unroll
        for (int i = 0; i < 2; i++) a[i] = AT[s * 65 + ty * 2 + i];
        *(float4*)&b[0] = *(const float4*)&Vs[s * 132 + tx * 8];
        *(float4*)&b[4] = *(const float4*)&Vs[s * 132 + tx * 8 + 4];
#pragma unroll
        for (int i = 0; i < 2; i++)
#pragma unroll
            for (int j = 0; j < 8; j++) O[i][j] += a[i] * b[j];
    }

#pragma unroll
    for (int i = 0; i < 2; i++) {
        int t = c * CH + ty * 2 + i;
        float4 o0 = make_float4(0.5f*O[i][0], 0.5f*O[i][1], 0.5f*O[i][2], 0.5f*O[i][3]);
        float4 o1 = make_float4(0.5f*O[i][4], 0.5f*O[i][5], 0.5f*O[i][6], 0.5f*O[i][7]);
        *(float4*)&g_gla[t * HD + h * DH + tx * 8]     = o0;
        *(float4*)&g_gla[t * HD + h * DH + tx * 8 + 4] = o1;
    }
}

// =============================================================================
// Causal flash attention, fp16 mma (m16n8k16). Q[128][68w], K[2][64][68w],
// V^T[128][36w], P[8][16][36w]. Writes 0.5*y into g_y.
// =============================================================================
#define QSW 68
#define VSW 36
#define ATTN_SMEM ((128*QSW + 2*64*QSW + 128*VSW + 8*16*VSW) * 4)  // 106496 B

__global__ void __launch_bounds__(256) attn_tc_kernel()
{
    extern __shared__ unsigned smA[];
    unsigned* Qs = smA;                          // [128][68]
    unsigned* Ks = Qs + 128 * QSW;               // [2][64][68]
    unsigned* Vs = Ks + 2 * 64 * QSW;            // [128][36] (V^T: row=d)
    unsigned* Pb = Vs + 128 * VSW;               // [8][16][36]

    const int qt = gridDim.x - 1 - blockIdx.x;
    const int h = blockIdx.y;
    const int kvh = h >> 2;
    const int tid = threadIdx.x;
    const int warp = tid >> 5, lane = tid & 31;
    const int gid = lane >> 2, tig = lane & 3;
    unsigned* Pw = Pb + warp * 16 * VSW;
    const float scale = 0.08838834764831845f;
    const int ktmax = 2 * qt + 1;

    const unsigned* sqw  = (const unsigned*)g_sqH;   // [t][1024w]
    const unsigned* skw  = (const unsigned*)g_skH;   // [t][256w]
    const unsigned* vtw  = (const unsigned*)g_vHT;   // [kvh*DH + d][1024w]

    // K_0 via cp.async (64 rows x 16 chunks)
    {
#pragma unroll
        for (int i = 0; i < 4; i++) {
            int idx = tid + i * 256;
            int r = idx >> 4, c4 = (idx & 15) * 4;
            cp16(&Ks[r * QSW + c4], &skw[(size_t)r * 256 + kvh * 64 + c4]);
        }
        asm volatile("cp.async.commit_group;");
    }

    // Q tile (128 rows x 16 chunks)
    for (int i = tid; i < 128 * 16; i += 256) {
        int r = i >> 4, c4 = (i & 15) * 4;
        *(uint4*)&Qs[r * QSW + c4] =
            *(const uint4*)&sqw[(size_t)(qt * 128 + r) * 1024 + h * 64 + c4];
    }

    const int rbase = qt * 128 + warp * 16;
    float m_i[2] = {-1e30f, -1e30f};
    float l_i[2] = {0.0f, 0.0f};
    float c[16][4];
#pragma unroll
    for (int ni = 0; ni < 16; ni++)
#pragma unroll
        for (int v = 0; v < 4; v++) c[ni][v] = 0.0f;

    for (int kt = 0; kt <= ktmax; kt++) {
        __syncthreads();

        // V^T_kt: 128 d-rows x 8 chunks of 4 words
#pragma unroll
        for (int i = 0; i < 4; i++) {
            int idx = tid + i * 256;
            int r = idx >> 3, c4 = (idx & 7) * 4;
            cp16(&Vs[r * VSW + c4],
                 &vtw[(size_t)(kvh * DH + r) * 1024 + kt * 32 + c4]);
        }
        asm volatile("cp.async.commit_group;");

        // K_{kt+1}
        {
            const int ktn = (kt < ktmax) ? kt + 1 : kt;
            unsigned* KB = Ks + ((kt + 1) & 1) * 64 * QSW;
#pragma unroll
            for (int i = 0; i < 4; i++) {
                int idx = tid + i * 256;
                int r = idx >> 4, c4 = (idx & 15) * 4;
                cp16(&KB[r * QSW + c4],
                     &skw[(size_t)(ktn * 64 + r) * 256 + kvh * 64 + c4]);
            }
            asm volatile("cp.async.commit_group;");
        }

        asm volatile("cp.async.wait_group 2;");
        __syncthreads();

        const unsigned* KB = Ks + (kt & 1) * 64 * QSW;
        const int smin = kt * 64;
        const bool active = (smin <= rbase + 15);

        if (active) {
            float sacc[8][4];
#pragma unroll
            for (int ni = 0; ni < 8; ni++)
#pragma unroll
                for (int v = 0; v < 4; v++) sacc[ni][v] = 0.0f;

            // QK: K=128 halves = 64 words -> 8 k16 steps (R15 bug: was 4)
#pragma unroll
            for (int k16 = 0; k16 < 8; k16++) {
                unsigned aq[4];
                int qr = warp * 16 + gid;
                aq[0] = Qs[qr * QSW + k16 * 8 + tig];
                aq[1] = Qs[(qr + 8) * QSW + k16 * 8 + tig];
                aq[2] = Qs[qr * QSW + k16 * 8 + tig + 4];
                aq[3] = Qs[(qr + 8) * QSW + k16 * 8 + tig + 4];
#pragma unroll
                for (int ni = 0; ni < 8; ni++) {
                    unsigned b0 = KB[(ni * 8 + gid) * QSW + k16 * 8 + tig];
                    unsigned b1 = KB[(ni * 8 + gid) * QSW + k16 * 8 + tig + 4];
                    mma_f16(sacc[ni], aq, b0, b1);
                }
            }

            const bool partial = (smin + 63 > rbase);
#pragma unroll
            for (int ni = 0; ni < 8; ni++)
#pragma unroll
                for (int v = 0; v < 4; v++) {
                    float sv = sacc[ni][v] * scale;
                    if (partial) {
                        int row = rbase + gid + (v >> 1) * 8;
                        int col = smin + ni * 8 + tig * 2 + (v & 1);
                        if (col > row) sv = -1e30f;
                    }
                    sacc[ni][v] = sv;
                }

#pragma unroll
            for (int h2 = 0; h2 < 2; h2++) {
                float rmax = -1e30f;
#pragma unroll
                for (int ni = 0; ni < 8; ni++)
                    rmax = fmaxf(rmax, fmaxf(sacc[ni][2 * h2], sacc[ni][2 * h2 + 1]));
                rmax = fmaxf(rmax, __shfl_xor_sync(0xffffffffu, rmax, 1));
                rmax = fmaxf(rmax, __shfl_xor_sync(0xffffffffu, rmax, 2));
                float mnew = fmaxf(m_i[h2], rmax);
                float alpha = __expf(m_i[h2] - mnew);
                float rsum = 0.0f;
#pragma unroll
                for (int ni = 0; ni < 8; ni++) {
                    float p0 = __expf(sacc[ni][2 * h2] - mnew);
                    float p1 = __expf(sacc[ni][2 * h2 + 1] - mnew);
                    sacc[ni][2 * h2] = p0;
                    sacc[ni][2 * h2 + 1] = p1;
                    rsum += p0 + p1;
                }
                rsum += __shfl_xor_sync(0xffffffffu, rsum, 1);
                rsum += __shfl_xor_sync(0xffffffffu, rsum, 2);
                l_i[h2] = l_i[h2] * alpha + rsum;
                m_i[h2] = mnew;
#pragma unroll
                for (int ni = 0; ni < 16; ni++) {
                    c[ni][2 * h2]     *= alpha;
                    c[ni][2 * h2 + 1] *= alpha;
                }
            }

            // P -> warp smem, fp16 packed (word = s-halves {2w,2w+1})
#pragma unroll
            for (int ni = 0; ni < 8; ni++) {
                Pw[gid * VSW + ni * 4 + tig]       = f2h2(sacc[ni][0], sacc[ni][1]);
                Pw[(gid + 8) * VSW + ni * 4 + tig] = f2h2(sacc[ni][2], sacc[ni][3]);
            }
        }

        asm volatile("cp.async.wait_group 1;");
        __syncthreads();

        if (active) {
            // PV: K=64 halves (s) = 32 words -> 4 k16 steps; B = V^T [d][s]
#pragma unroll
            for (int k16 = 0; k16 < 4; k16++) {
                unsigned ap[4];
                ap[0] = Pw[gid * VSW + k16 * 8 + tig];
                ap[1] = Pw[(gid + 8) * VSW + k16 * 8 + tig];
                ap[2] = Pw[gid * VSW + k16 * 8 + tig + 4];
                ap[3] = Pw[(gid + 8) * VSW + k16 * 8 + tig + 4];
#pragma unroll
                for (int ni = 0; ni < 16; ni++) {
                    unsigned b0 = Vs[(ni * 8 + gid) * VSW + k16 * 8 + tig];
                    unsigned b1 = Vs[(ni * 8 + gid) * VSW + k16 * 8 + tig + 4];
                    mma_f16(c[ni], ap, b0, b1);
                }
            }
        }
    }

    const float h0 = 0.5f / l_i[0];
    const float h1 = 0.5f / l_i[1];
    const int r0 = rbase + gid, r1 = r0 + 8;
#pragma unroll
    for (int ni = 0; ni < 16; ni++) {
        int col = h * DH + ni * 8 + tig * 2;
        *(float2*)&g_y[(size_t)r0 * HD + col] = make_float2(c[ni][0] * h0, c[ni][1] * h0);
        *(float2*)&g_y[(size_t)r1 * HD + col] = make_float2(c[ni][2] * h1, c[ni][3] * h1);
    }
}

// =============================================================================
// host launcher — fork/join: GLA chain (stream A) || attention (stream B)
// =============================================================================
extern "C" void kernel_launch(void* const* d_in, const int* in_sizes, int n_in,
                              void* d_out, int out_size)
{
    (void)in_sizes; (void)n_in; (void)out_size;
    const float* hs = (const float*)d_in[0];
    const float* Wq = (const float*)d_in[1];
    const float* Wk = (const float*)d_in[2];
    const float* Wv = (const float*)d_in[3];
    const float* Wo = (const float*)d_in[4];
    float* out = (float*)d_out;

    unsigned *p_hsH, *p_WqH, *p_WkH, *p_WvH, *p_WoH;
    cudaGetSymbolAddress((void**)&p_hsH, g_hsH);
    cudaGetSymbolAddress((void**)&p_WqH, g_WqH);
    cudaGetSymbolAddress((void**)&p_WkH, g_WkH);
    cudaGetSymbolAddress((void**)&p_WvH, g_WvH);
    cudaGetSymbolAddress((void**)&p_WoH, g_WoH);

    static cudaStream_t sA = nullptr, sB = nullptr;
    static cudaEvent_t ev0, evP, evA, evB;
    if (sA == nullptr) {
        cudaStreamCreateWithFlags(&sA, cudaStreamNonBlocking);
        cudaStreamCreateWithFlags(&sB, cudaStreamNonBlocking);
        cudaEventCreateWithFlags(&ev0, cudaEventDisableTiming);
        cudaEventCreateWithFlags(&evP, cudaEventDisableTiming);
        cudaEventCreateWithFlags(&evA, cudaEventDisableTiming);
        cudaEventCreateWithFlags(&evB, cudaEventDisableTiming);
    }

    const int smem3 = (2 * 128 * 65 + 128 * 132 + 64 * 132 + 64 * 65) * 4;
    cudaFuncSetAttribute(proj_kernel,      cudaFuncAttributeMaxDynamicSharedMemorySize, GEMM_SMEM);
    cudaFuncSetAttribute(wo_kernel,        cudaFuncAttributeMaxDynamicSharedMemorySize, GEMM_SMEM);
    cudaFuncSetAttribute(gla_pass1_kernel, cudaFuncAttributeMaxDynamicSharedMemorySize, P1_SMEM);
    cudaFuncSetAttribute(gla_pass3_kernel, cudaFuncAttributeMaxDynamicSharedMemorySize, smem3);
    cudaFuncSetAttribute(attn_tc_kernel,   cudaFuncAttributeMaxDynamicSharedMemorySize, ATTN_SMEM);

    // --- fork Wo transpose+pack onto stream A early ---
    cudaEventRecord(ev0, 0);
    cudaStreamWaitEvent(sA, ev0, 0);
    transpose_cvt_h_kernel<<<dim3(HIDN / 32, HD / 32), 256, 0, sA>>>(
        Wo, (__half*)p_WoH, HD, HIDN);

    // --- main stream: rope + hs pack + weight transposes + projections ---
    rope_table_kernel<<<NTOK, 64>>>();
    cvt_h_kernel<<<4096, 256>>>((const float4*)hs, (uint2*)p_hsH, NTOK * HIDN / 4);
    transpose_cvt_h_kernel<<<dim3(HD / 32,  HIDN / 32), 256>>>(Wq, (__half*)p_WqH, HIDN, HD);
    transpose_cvt_h_kernel<<<dim3(KVD / 32, HIDN / 32), 256>>>(Wk, (__half*)p_WkH, HIDN, KVD);
    transpose_cvt_h_kernel<<<dim3(KVD / 32, HIDN / 32), 256>>>(Wv, (__half*)p_WvH, HIDN, KVD);
    proj_kernel<<<dim3(24, 16), 256, GEMM_SMEM>>>();
    cudaEventRecord(evP, 0);

    // --- stream A: GLA chain ---
    cudaStreamWaitEvent(sA, evP, 0);
    gla_pass1_kernel<<<dim3(NCH, NKV, 2), 256, P1_SMEM, sA>>>();
    gla_scan_kernel<<<dim3(NKV, DH), 128, 0, sA>>>();
    gla_pass3_kernel<<<dim3(NCH, NH), 512, smem3, sA>>>();
    cudaEventRecord(evA, sA);

    // --- stream B: V transpose (fp16) + causal flash attention (fp16 mma) ---
    cudaStreamWaitEvent(sB, evP, 0);
    transpose_vh_kernel<<<dim3(NTOK / 32, DH / 32, NKV), 256, 0, sB>>>();
    attn_tc_kernel<<<dim3(NTOK / 128, NH), 256, ATTN_SMEM, sB>>>();
    cudaEventRecord(evB, sB);

    // --- join, combine, output projection ---
    cudaStreamWaitEvent(0, evA, 0);
    cudaStreamWaitEvent(0, evB, 0);
    combine_kernel<<<NTOK * HD / 4 / 256, 256>>>();
    wo_kernel<<<dim3(16, 16), 256, GEMM_SMEM>>>(out);
}